// round 1
// baseline (speedup 1.0000x reference)
#include <cuda_runtime.h>
#include <cstddef>

// Problem constants (fixed by the dataset)
#define BB 4
#define TT 2048
#define CC 1024
#define HH 16
#define DD 64
#define RR 8
#define MM (BB*TT)        // 8192
#define NQKV (3*CC)       // 3072

// Scratch (device globals -- no allocation allowed)
__device__ float g_q[(size_t)BB*HH*TT*DD];   // [B,H,T,D]
__device__ float g_k[(size_t)BB*HH*TT*DD];
__device__ float g_v[(size_t)BB*HH*TT*DD];
__device__ float g_y[(size_t)MM*CC];          // attention output [B,T,C]
__device__ float g_t[(size_t)MM*RR];          // LoRA intermediate x@A^T

// ---------------------------------------------------------------------------
// LoRA intermediate: t[m, r] = sum_k X[m,k] * A[r,k]   (one warp per row m)
// SRC==1 reads X from g_y (for the proj LoRA).
// ---------------------------------------------------------------------------
template<int SRC>
__global__ void lora_kernel(const float* __restrict__ Xin, const float* __restrict__ A) {
    const float* X = (SRC == 1) ? g_y : Xin;
    int warp = (blockIdx.x * blockDim.x + threadIdx.x) >> 5;
    int lane = threadIdx.x & 31;
    const float* xr = X + (size_t)warp * CC;
    float acc[RR];
#pragma unroll
    for (int r = 0; r < RR; r++) acc[r] = 0.f;
    for (int k = lane; k < CC; k += 32) {
        float xv = xr[k];
#pragma unroll
        for (int r = 0; r < RR; r++) acc[r] = fmaf(xv, __ldg(&A[r*CC + k]), acc[r]);
    }
#pragma unroll
    for (int r = 0; r < RR; r++) {
        acc[r] += __shfl_xor_sync(0xffffffffu, acc[r], 16);
        acc[r] += __shfl_xor_sync(0xffffffffu, acc[r], 8);
        acc[r] += __shfl_xor_sync(0xffffffffu, acc[r], 4);
        acc[r] += __shfl_xor_sync(0xffffffffu, acc[r], 2);
        acc[r] += __shfl_xor_sync(0xffffffffu, acc[r], 1);
    }
    if (lane == 0) {
#pragma unroll
        for (int r = 0; r < RR; r++) g_t[(size_t)warp*RR + r] = acc[r];
    }
}

// ---------------------------------------------------------------------------
// C = X @ W^T + bias + (g_t) @ Bl^T
// 64x64 block tile, BK=16, 256 threads, 4x4 microtile.
// MODE 0: QKV — scatter into g_q/g_k/g_v ([B,H,T,D]) and write query/key outs.
// MODE 1: proj — X is g_y, plain write to out0 ([M, C]).
// ---------------------------------------------------------------------------
template<int MODE>
__global__ void gemm_lora_kernel(const float* __restrict__ Xin,
                                 const float* __restrict__ W,
                                 const float* __restrict__ bias,
                                 const float* __restrict__ Bl,
                                 float* __restrict__ out0,
                                 float* __restrict__ out1)
{
    __shared__ float Xs[16][64];
    __shared__ float Ws[16][64];
    const float* X = (MODE == 1) ? g_y : Xin;
    int tid = threadIdx.x;
    int bm = blockIdx.y * 64;
    int bn = blockIdx.x * 64;
    int tx = tid & 15, ty = tid >> 4;
    int lr = tid >> 2;            // row within tile for loading (0..63)
    int lk = (tid & 3) * 4;       // k offset for loading
    const float* Xg = X + (size_t)(bm + lr) * CC + lk;
    const float* Wg = W + (size_t)(bn + lr) * CC + lk;

    float acc[4][4];
#pragma unroll
    for (int i = 0; i < 4; i++)
#pragma unroll
        for (int j = 0; j < 4; j++) acc[i][j] = 0.f;

    for (int k0 = 0; k0 < CC; k0 += 16) {
        float4 xa = *(const float4*)(Xg + k0);
        float4 wa = *(const float4*)(Wg + k0);
        Xs[lk+0][lr] = xa.x; Xs[lk+1][lr] = xa.y; Xs[lk+2][lr] = xa.z; Xs[lk+3][lr] = xa.w;
        Ws[lk+0][lr] = wa.x; Ws[lk+1][lr] = wa.y; Ws[lk+2][lr] = wa.z; Ws[lk+3][lr] = wa.w;
        __syncthreads();
#pragma unroll
        for (int kk = 0; kk < 16; kk++) {
            float4 a = *(const float4*)&Xs[kk][ty*4];
            float4 b = *(const float4*)&Ws[kk][tx*4];
            acc[0][0] = fmaf(a.x, b.x, acc[0][0]); acc[0][1] = fmaf(a.x, b.y, acc[0][1]);
            acc[0][2] = fmaf(a.x, b.z, acc[0][2]); acc[0][3] = fmaf(a.x, b.w, acc[0][3]);
            acc[1][0] = fmaf(a.y, b.x, acc[1][0]); acc[1][1] = fmaf(a.y, b.y, acc[1][1]);
            acc[1][2] = fmaf(a.y, b.z, acc[1][2]); acc[1][3] = fmaf(a.y, b.w, acc[1][3]);
            acc[2][0] = fmaf(a.z, b.x, acc[2][0]); acc[2][1] = fmaf(a.z, b.y, acc[2][1]);
            acc[2][2] = fmaf(a.z, b.z, acc[2][2]); acc[2][3] = fmaf(a.z, b.w, acc[2][3]);
            acc[3][0] = fmaf(a.w, b.x, acc[3][0]); acc[3][1] = fmaf(a.w, b.y, acc[3][1]);
            acc[3][2] = fmaf(a.w, b.z, acc[3][2]); acc[3][3] = fmaf(a.w, b.w, acc[3][3]);
        }
        __syncthreads();
    }

    // Epilogue: + bias + LoRA (rank 8), then scatter / store.
    int m0 = bm + ty*4, n0 = bn + tx*4;
    float tl[4][RR], bl[4][RR], bs[4];
#pragma unroll
    for (int i = 0; i < 4; i++)
#pragma unroll
        for (int r = 0; r < RR; r++) tl[i][r] = g_t[(size_t)(m0+i)*RR + r];
#pragma unroll
    for (int j = 0; j < 4; j++) {
        bs[j] = bias[n0+j];
#pragma unroll
        for (int r = 0; r < RR; r++) bl[j][r] = Bl[(size_t)(n0+j)*RR + r];
    }
#pragma unroll
    for (int i = 0; i < 4; i++) {
#pragma unroll
        for (int j = 0; j < 4; j++) {
            float v = acc[i][j] + bs[j];
#pragma unroll
            for (int r = 0; r < RR; r++) v = fmaf(tl[i][r], bl[j][r], v);
            int m = m0 + i, n = n0 + j;
            if (MODE == 0) {
                int sec = n >> 10;          // 0=q, 1=k, 2=v  (C = 1024)
                int cci = n & 1023;
                int h = cci >> 6, dd = cci & 63;
                int bi = m >> 11, ti = m & 2047;   // T = 2048
                float* dst = (sec == 0) ? g_q : ((sec == 1) ? g_k : g_v);
                dst[(size_t)(((bi*HH) + h)*TT + ti)*DD + dd] = v;
                if (sec == 0)      out0[(size_t)m*CC + cci] = v;  // query
                else if (sec == 1) out1[(size_t)m*CC + cci] = v;  // key
            } else {
                out0[(size_t)m*CC + n] = v;
            }
        }
    }
}

// ---------------------------------------------------------------------------
// Causal flash attention fp32, d=64. Br=64 queries, Bc=32 keys per iter.
// 256 threads: thread owns (r = tid/4, g = tid%4): 8 score cols (c = cc*4+g)
// and 16 output dims (d = g*16..g*16+15).
// ---------------------------------------------------------------------------
__global__ void flash_kernel() {
    __shared__ float Qs[64*68];
    __shared__ float Ks[32*68];
    __shared__ float Vs[32*68];
    __shared__ float Ps[64*36];
    int bh = blockIdx.y;                   // b*H + h
    int qi = blockIdx.x;
    int tid = threadIdx.x;
    int r = tid >> 2, g = tid & 3;
    int row0 = qi * 64;
    int myrow = row0 + r;
    const float* Qg = g_q + ((size_t)bh*TT + row0) * DD;
    const float* Kg = g_k + (size_t)bh*TT*DD;
    const float* Vg = g_v + (size_t)bh*TT*DD;

#pragma unroll
    for (int i = 0; i < 16; i++) {
        int e = tid + i*256;
        Qs[(e>>6)*68 + (e&63)] = Qg[e];
    }
    float O[16];
#pragma unroll
    for (int i = 0; i < 16; i++) O[i] = 0.f;
    float m_r = -1e30f, l_r = 0.f;

    int jmax = 2*qi + 1;
    for (int j = 0; j <= jmax; j++) {
        int col0 = j*32;
#pragma unroll
        for (int i = 0; i < 8; i++) {
            int e = tid + i*256;
            Ks[(e>>6)*68 + (e&63)] = Kg[(size_t)col0*DD + e];
            Vs[(e>>6)*68 + (e&63)] = Vg[(size_t)col0*DD + e];
        }
        __syncthreads();

        float s[8];
#pragma unroll
        for (int cc = 0; cc < 8; cc++) s[cc] = 0.f;
#pragma unroll
        for (int d4 = 0; d4 < 16; d4++) {
            float4 q4 = *(const float4*)&Qs[r*68 + d4*4];
#pragma unroll
            for (int cc = 0; cc < 8; cc++) {
                int c = cc*4 + g;
                float4 k4 = *(const float4*)&Ks[c*68 + d4*4];
                s[cc] += q4.x*k4.x + q4.y*k4.y + q4.z*k4.z + q4.w*k4.w;
            }
        }
        float mx = -1e30f;
#pragma unroll
        for (int cc = 0; cc < 8; cc++) {
            int col = col0 + cc*4 + g;
            s[cc] = (col <= myrow) ? s[cc]*0.125f : -1e30f;   // 1/sqrt(64)
            mx = fmaxf(mx, s[cc]);
        }
        mx = fmaxf(mx, __shfl_xor_sync(0xffffffffu, mx, 1));
        mx = fmaxf(mx, __shfl_xor_sync(0xffffffffu, mx, 2));
        float m_new = fmaxf(m_r, mx);
        float lt = 0.f;
#pragma unroll
        for (int cc = 0; cc < 8; cc++) {
            float p = __expf(s[cc] - m_new);
            Ps[r*36 + cc*4 + g] = p;
            lt += p;
        }
        lt += __shfl_xor_sync(0xffffffffu, lt, 1);
        lt += __shfl_xor_sync(0xffffffffu, lt, 2);
        float alpha = __expf(m_r - m_new);
        m_r = m_new;
        l_r = l_r*alpha + lt;
#pragma unroll
        for (int i = 0; i < 16; i++) O[i] *= alpha;
        __syncwarp();     // P row written/read within the same warp-group of 4

#pragma unroll
        for (int c = 0; c < 32; c++) {
            float p = Ps[r*36 + c];
            const float* vp = &Vs[c*68 + g*16];
            float4 v0 = *(const float4*)(vp + 0);
            float4 v1 = *(const float4*)(vp + 4);
            float4 v2 = *(const float4*)(vp + 8);
            float4 v3 = *(const float4*)(vp + 12);
            O[0]  = fmaf(p, v0.x, O[0]);  O[1]  = fmaf(p, v0.y, O[1]);
            O[2]  = fmaf(p, v0.z, O[2]);  O[3]  = fmaf(p, v0.w, O[3]);
            O[4]  = fmaf(p, v1.x, O[4]);  O[5]  = fmaf(p, v1.y, O[5]);
            O[6]  = fmaf(p, v1.z, O[6]);  O[7]  = fmaf(p, v1.w, O[7]);
            O[8]  = fmaf(p, v2.x, O[8]);  O[9]  = fmaf(p, v2.y, O[9]);
            O[10] = fmaf(p, v2.z, O[10]); O[11] = fmaf(p, v2.w, O[11]);
            O[12] = fmaf(p, v3.x, O[12]); O[13] = fmaf(p, v3.y, O[13]);
            O[14] = fmaf(p, v3.z, O[14]); O[15] = fmaf(p, v3.w, O[15]);
        }
        __syncthreads();   // protect Ks/Vs before the next tile's load
    }

    float inv = 1.0f / l_r;
    int h = bh & (HH - 1), bi = bh >> 4;
    float* yr = g_y + ((size_t)(bi*TT + myrow))*CC + h*DD + g*16;
#pragma unroll
    for (int i = 0; i < 16; i++) yr[i] = O[i]*inv;
}

// ---------------------------------------------------------------------------
extern "C" void kernel_launch(void* const* d_in, const int* in_sizes, int n_in,
                              void* d_out, int out_size) {
    const float* x  = (const float*)d_in[0];
    const float* aw = (const float*)d_in[1];
    const float* ab = (const float*)d_in[2];
    const float* aA = (const float*)d_in[3];
    const float* aB = (const float*)d_in[4];
    const float* pw = (const float*)d_in[5];
    const float* pb = (const float*)d_in[6];
    const float* pA = (const float*)d_in[7];
    const float* pB = (const float*)d_in[8];
    (void)in_sizes; (void)n_in; (void)out_size;

    float* out  = (float*)d_out;                    // [B,T,C]
    float* outQ = out + (size_t)MM*CC;              // query [B,T,C]
    float* outK = out + (size_t)2*MM*CC;            // key   [B,T,C]

    // 1) LoRA intermediate for c_attn: g_t = x @ A^T
    lora_kernel<0><<<MM/8, 256>>>(x, aA);
    // 2) QKV GEMM + bias + LoRA, scatter q/k/v, emit query/key outputs
    gemm_lora_kernel<0><<<dim3(NQKV/64, MM/64), 256>>>(x, aw, ab, aB, outQ, outK);
    // 3) Causal flash attention -> g_y
    flash_kernel<<<dim3(TT/64, BB*HH), 256>>>();
    // 4) LoRA intermediate for c_proj: g_t = y @ A^T
    lora_kernel<1><<<MM/8, 256>>>(nullptr, pA);
    // 5) Proj GEMM + bias + LoRA -> out
    gemm_lora_kernel<1><<<dim3(CC/64, MM/64), 256>>>(nullptr, pw, pb, pB, out, nullptr);
}

// round 4
// speedup vs baseline: 1.3815x; 1.3815x over previous
#include <cuda_runtime.h>
#include <cuda_bf16.h>
#include <cstdint>
#include <cstddef>

// Problem constants (fixed by the dataset)
#define BB 4
#define TT 2048
#define CC 1024
#define HH 16
#define DD 64
#define RR 8
#define MM (BB*TT)        // 8192
#define NQKV (3*CC)       // 3072

// Scratch (device globals -- no allocation allowed)
__device__ float g_q[(size_t)BB*HH*TT*DD];   // [B,H,T,D]
__device__ float g_k[(size_t)BB*HH*TT*DD];
__device__ float g_v[(size_t)BB*HH*TT*DD];
__device__ float g_y[(size_t)MM*CC];         // attention output [B,T,C]
__device__ float g_t[(size_t)MM*RR];         // LoRA intermediate x@A^T
// bf16 split buffers (A side reused for x then y; B side for attn W then proj W)
__device__ __nv_bfloat16 g_ah[(size_t)MM*CC];
__device__ __nv_bfloat16 g_al[(size_t)MM*CC];
__device__ __nv_bfloat16 g_bh[(size_t)NQKV*CC];
__device__ __nv_bfloat16 g_bl[(size_t)NQKV*CC];

// ---------------------------------------------------------------------------
// Helpers (base-target ISA only: cp.async / ldmatrix / mma.sync)
// ---------------------------------------------------------------------------
__device__ __forceinline__ uint32_t smem_u32(const void* p) {
    uint32_t a;
    asm("{ .reg .u64 t; cvta.to.shared.u64 t, %1; cvt.u32.u64 %0, t; }"
        : "=r"(a) : "l"(p));
    return a;
}
#define SWZ128(off) ((off) ^ (((off) >> 3) & 0x70))

#define CP_ASYNC16(dst, src) \
    asm volatile("cp.async.cg.shared.global [%0], [%1], 16;" :: "r"(dst), "l"(src))
#define CP_COMMIT() asm volatile("cp.async.commit_group;" ::: "memory")
#define CP_WAIT(n)  asm volatile("cp.async.wait_group %0;" :: "n"(n) : "memory")

#define LDSM_X4(r, a) \
    asm volatile("ldmatrix.sync.aligned.m8n8.x4.shared.b16 {%0,%1,%2,%3}, [%4];" \
                 : "=r"((r)[0]), "=r"((r)[1]), "=r"((r)[2]), "=r"((r)[3]) : "r"(a))

#define MMA16816(d, a, b0, b1) \
    asm volatile("mma.sync.aligned.m16n8k16.row.col.f32.bf16.bf16.f32 " \
                 "{%0,%1,%2,%3}, {%4,%5,%6,%7}, {%8,%9}, {%0,%1,%2,%3};" \
                 : "+f"((d)[0]), "+f"((d)[1]), "+f"((d)[2]), "+f"((d)[3]) \
                 : "r"((a)[0]), "r"((a)[1]), "r"((a)[2]), "r"((a)[3]), \
                   "r"(b0), "r"(b1))

// ---------------------------------------------------------------------------
// fp32 -> bf16 hi/lo split conversion.
// SRCY=1: read from g_y. DSTB=1: write g_bh/g_bl, else g_ah/g_al.
// ---------------------------------------------------------------------------
template<int SRCY, int DSTB>
__global__ void conv_split(const float* __restrict__ src, int n4) {
    int i = blockIdx.x * blockDim.x + threadIdx.x;
    if (i >= n4) return;
    const float4* s = (const float4*)(SRCY ? (const float*)g_y : src);
    float4 v = s[i];
    __nv_bfloat16* H = DSTB ? g_bh : g_ah;
    __nv_bfloat16* L = DSTB ? g_bl : g_al;
    __nv_bfloat16 h0 = __float2bfloat16(v.x), h1 = __float2bfloat16(v.y);
    __nv_bfloat16 h2 = __float2bfloat16(v.z), h3 = __float2bfloat16(v.w);
    __nv_bfloat162 ph0; ph0.x = h0; ph0.y = h1;
    __nv_bfloat162 ph1; ph1.x = h2; ph1.y = h3;
    __nv_bfloat162 pl0; pl0.x = __float2bfloat16(v.x - __bfloat162float(h0));
                        pl0.y = __float2bfloat16(v.y - __bfloat162float(h1));
    __nv_bfloat162 pl1; pl1.x = __float2bfloat16(v.z - __bfloat162float(h2));
                        pl1.y = __float2bfloat16(v.w - __bfloat162float(h3));
    ((__nv_bfloat162*)H)[2*i]   = ph0;
    ((__nv_bfloat162*)H)[2*i+1] = ph1;
    ((__nv_bfloat162*)L)[2*i]   = pl0;
    ((__nv_bfloat162*)L)[2*i+1] = pl1;
}

// ---------------------------------------------------------------------------
// LoRA intermediate: t[m, r] = sum_k X[m,k] * A[r,k]   (one warp per row m)
// ---------------------------------------------------------------------------
template<int SRC>
__global__ void lora_kernel(const float* __restrict__ Xin, const float* __restrict__ A) {
    const float* X = (SRC == 1) ? g_y : Xin;
    int warp = (blockIdx.x * blockDim.x + threadIdx.x) >> 5;
    int lane = threadIdx.x & 31;
    const float* xr = X + (size_t)warp * CC;
    float acc[RR];
#pragma unroll
    for (int r = 0; r < RR; r++) acc[r] = 0.f;
    for (int k = lane; k < CC; k += 32) {
        float xv = xr[k];
#pragma unroll
        for (int r = 0; r < RR; r++) acc[r] = fmaf(xv, __ldg(&A[r*CC + k]), acc[r]);
    }
#pragma unroll
    for (int r = 0; r < RR; r++) {
        acc[r] += __shfl_xor_sync(0xffffffffu, acc[r], 16);
        acc[r] += __shfl_xor_sync(0xffffffffu, acc[r], 8);
        acc[r] += __shfl_xor_sync(0xffffffffu, acc[r], 4);
        acc[r] += __shfl_xor_sync(0xffffffffu, acc[r], 2);
        acc[r] += __shfl_xor_sync(0xffffffffu, acc[r], 1);
    }
    if (lane == 0) {
#pragma unroll
        for (int r = 0; r < RR; r++) g_t[(size_t)warp*RR + r] = acc[r];
    }
}

// ---------------------------------------------------------------------------
// bf16-split HMMA GEMM (mma.sync m16n8k16) + bias + rank-8 LoRA epilogue.
// CTA tile 128x128, 8 warps of 64x32 (warp_m = wid>>2 in {0,1}, warp_n = wid&3).
// K chunks of 64, double-buffered via cp.async (2 stages x 64KB).
// MODE 0: QKV -> scatter q/k/v + write query/key outputs.
// MODE 1: proj -> plain [M,C] output.
// ---------------------------------------------------------------------------
#define STAGE_BYTES 65536
#define OFF_AH 0
#define OFF_AL 16384
#define OFF_BH 32768
#define OFF_BL 49152

template<int MODE>
__global__ void __launch_bounds__(256) mma_gemm(const float* __restrict__ bias,
                                                const float* __restrict__ Blora,
                                                float* __restrict__ out0,
                                                float* __restrict__ out1)
{
    extern __shared__ char smem_raw[];
    uint32_t raw = smem_u32(smem_raw);
    uint32_t sb = (raw + 1023u) & ~1023u;          // 1KB-aligned base

    int tid  = threadIdx.x;
    int wid  = tid >> 5, lane = tid & 31;
    int wm   = wid >> 2;       // 0..1 -> 64-row slab
    int wn   = wid & 3;        // 0..3 -> 32-col slab
    int bm = blockIdx.y * 128;
    int bn = blockIdx.x * 128;

    // loader indices: per tile, 4 x 16B per thread
    int lrow = tid >> 1;                  // 0..127  (2 threads per row)
    int lq   = (tid & 1) * 4;             // uint4 index within row (0 or 4)

    float acc[4][4][4];
#pragma unroll
    for (int i = 0; i < 4; i++)
#pragma unroll
        for (int j = 0; j < 4; j++)
#pragma unroll
            for (int c = 0; c < 4; c++) acc[i][j][c] = 0.f;

    auto load_chunk = [&](int stage, int k0) {
        uint32_t base = sb + stage * STAGE_BYTES;
        const __nv_bfloat16* srcs[4] = { g_ah, g_al, g_bh, g_bl };
#pragma unroll
        for (int t = 0; t < 4; t++) {
            int grow = (t < 2) ? (bm + lrow) : (bn + lrow);
            const __nv_bfloat16* sp = srcs[t] + (size_t)grow * CC + k0 + lq * 8;
#pragma unroll
            for (int j = 0; j < 4; j++) {
                uint32_t boff = SWZ128((uint32_t)(lrow * 128 + (lq + j) * 16));
                CP_ASYNC16(base + t * 16384 + boff, sp + j * 8);
            }
        }
        CP_COMMIT();
    };

    const int NCHUNK = CC / 64;   // 16
    load_chunk(0, 0);

    for (int ch = 0; ch < NCHUNK; ++ch) {
        if (ch + 1 < NCHUNK) {
            load_chunk((ch + 1) & 1, (ch + 1) * 64);
            CP_WAIT(1);
        } else {
            CP_WAIT(0);
        }
        __syncthreads();
        uint32_t base = sb + (ch & 1) * STAGE_BYTES;

#pragma unroll
        for (int ks = 0; ks < 4; ks++) {
            uint32_t ah[4][4], al[4][4];
#pragma unroll
            for (int ma = 0; ma < 4; ma++) {
                int row = wm * 64 + ma * 16 + (lane & 15);
                uint32_t kb = ks * 32 + ((lane >> 4) << 4);
                uint32_t off = SWZ128((uint32_t)(row * 128) + kb);
                LDSM_X4(ah[ma], base + OFF_AH + off);
                LDSM_X4(al[ma], base + OFF_AL + off);
            }
            uint32_t bh[2][4], bl[2][4];
#pragma unroll
            for (int nb = 0; nb < 2; nb++) {
                int row = wn * 32 + nb * 16 + (lane & 7) + ((lane >> 4) << 3);
                uint32_t kb = ks * 32 + (((lane >> 3) & 1) << 4);
                uint32_t off = SWZ128((uint32_t)(row * 128) + kb);
                LDSM_X4(bh[nb], base + OFF_BH + off);
                LDSM_X4(bl[nb], base + OFF_BL + off);
            }
#pragma unroll
            for (int ma = 0; ma < 4; ma++) {
#pragma unroll
                for (int na = 0; na < 4; na++) {
                    int nb = na >> 1, h = (na & 1) * 2;
                    MMA16816(acc[ma][na], ah[ma], bh[nb][h], bh[nb][h+1]);
                    MMA16816(acc[ma][na], ah[ma], bl[nb][h], bl[nb][h+1]);
                    MMA16816(acc[ma][na], al[ma], bh[nb][h], bh[nb][h+1]);
                }
            }
        }
        __syncthreads();
    }

    // ---- epilogue: + bias + LoRA, write out (scatter for MODE 0) ----
#pragma unroll
    for (int ma = 0; ma < 4; ma++) {
        int m0 = bm + wm * 64 + ma * 16 + (lane >> 2);
        int m1 = m0 + 8;
        float4 t0a = *(const float4*)&g_t[(size_t)m0 * RR];
        float4 t0b = *(const float4*)&g_t[(size_t)m0 * RR + 4];
        float4 t1a = *(const float4*)&g_t[(size_t)m1 * RR];
        float4 t1b = *(const float4*)&g_t[(size_t)m1 * RR + 4];
#pragma unroll
        for (int na = 0; na < 4; na++) {
            int n0 = bn + wn * 32 + na * 8 + (lane & 3) * 2;
            int n1 = n0 + 1;
            float4 b0a = *(const float4*)&Blora[(size_t)n0 * RR];
            float4 b0b = *(const float4*)&Blora[(size_t)n0 * RR + 4];
            float4 b1a = *(const float4*)&Blora[(size_t)n1 * RR];
            float4 b1b = *(const float4*)&Blora[(size_t)n1 * RR + 4];
            float bs0 = __ldg(&bias[n0]), bs1 = __ldg(&bias[n1]);
            float v00 = acc[ma][na][0] + bs0
                + t0a.x*b0a.x + t0a.y*b0a.y + t0a.z*b0a.z + t0a.w*b0a.w
                + t0b.x*b0b.x + t0b.y*b0b.y + t0b.z*b0b.z + t0b.w*b0b.w;
            float v01 = acc[ma][na][1] + bs1
                + t0a.x*b1a.x + t0a.y*b1a.y + t0a.z*b1a.z + t0a.w*b1a.w
                + t0b.x*b1b.x + t0b.y*b1b.y + t0b.z*b1b.z + t0b.w*b1b.w;
            float v10 = acc[ma][na][2] + bs0
                + t1a.x*b0a.x + t1a.y*b0a.y + t1a.z*b0a.z + t1a.w*b0a.w
                + t1b.x*b0b.x + t1b.y*b0b.y + t1b.z*b0b.z + t1b.w*b0b.w;
            float v11 = acc[ma][na][3] + bs1
                + t1a.x*b1a.x + t1a.y*b1a.y + t1a.z*b1a.z + t1a.w*b1a.w
                + t1b.x*b1b.x + t1b.y*b1b.y + t1b.z*b1b.z + t1b.w*b1b.w;

            if (MODE == 0) {
                int sec = n0 >> 10;            // 0=q, 1=k, 2=v
                int cci = n0 & 1023;
                int h = cci >> 6, dd = cci & 63;   // dd even, pair stays in head
                float* dst = (sec == 0) ? g_q : ((sec == 1) ? g_k : g_v);
                {
                    int bi = m0 >> 11, ti = m0 & 2047;
                    float2 p; p.x = v00; p.y = v01;
                    *(float2*)&dst[((size_t)((bi*HH) + h)*TT + ti)*DD + dd] = p;
                    if (sec == 0)      *(float2*)&out0[(size_t)m0*CC + cci] = p;
                    else if (sec == 1) *(float2*)&out1[(size_t)m0*CC + cci] = p;
                }
                {
                    int bi = m1 >> 11, ti = m1 & 2047;
                    float2 p; p.x = v10; p.y = v11;
                    *(float2*)&dst[((size_t)((bi*HH) + h)*TT + ti)*DD + dd] = p;
                    if (sec == 0)      *(float2*)&out0[(size_t)m1*CC + cci] = p;
                    else if (sec == 1) *(float2*)&out1[(size_t)m1*CC + cci] = p;
                }
            } else {
                float2 p0; p0.x = v00; p0.y = v01;
                float2 p1; p1.x = v10; p1.y = v11;
                *(float2*)&out0[(size_t)m0*CC + n0] = p0;
                *(float2*)&out0[(size_t)m1*CC + n0] = p1;
            }
        }
    }
}

// ---------------------------------------------------------------------------
// Causal flash attention fp32, d=64. Br=64 queries, Bc=32 keys per iter.
// ---------------------------------------------------------------------------
__global__ void flash_kernel() {
    __shared__ float Qs[64*68];
    __shared__ float Ks[32*68];
    __shared__ float Vs[32*68];
    __shared__ float Ps[64*36];
    int bh = blockIdx.y;
    int qi = blockIdx.x;
    int tid = threadIdx.x;
    int r = tid >> 2, g = tid & 3;
    int row0 = qi * 64;
    int myrow = row0 + r;
    const float* Qg = g_q + ((size_t)bh*TT + row0) * DD;
    const float* Kg = g_k + (size_t)bh*TT*DD;
    const float* Vg = g_v + (size_t)bh*TT*DD;

#pragma unroll
    for (int i = 0; i < 16; i++) {
        int e = tid + i*256;
        Qs[(e>>6)*68 + (e&63)] = Qg[e];
    }
    float O[16];
#pragma unroll
    for (int i = 0; i < 16; i++) O[i] = 0.f;
    float m_r = -1e30f, l_r = 0.f;

    int jmax = 2*qi + 1;
    for (int j = 0; j <= jmax; j++) {
        int col0 = j*32;
#pragma unroll
        for (int i = 0; i < 8; i++) {
            int e = tid + i*256;
            Ks[(e>>6)*68 + (e&63)] = Kg[(size_t)col0*DD + e];
            Vs[(e>>6)*68 + (e&63)] = Vg[(size_t)col0*DD + e];
        }
        __syncthreads();

        float s[8];
#pragma unroll
        for (int cc = 0; cc < 8; cc++) s[cc] = 0.f;
#pragma unroll
        for (int d4 = 0; d4 < 16; d4++) {
            float4 q4 = *(const float4*)&Qs[r*68 + d4*4];
#pragma unroll
            for (int cc = 0; cc < 8; cc++) {
                int c = cc*4 + g;
                float4 k4 = *(const float4*)&Ks[c*68 + d4*4];
                s[cc] += q4.x*k4.x + q4.y*k4.y + q4.z*k4.z + q4.w*k4.w;
            }
        }
        float mx = -1e30f;
#pragma unroll
        for (int cc = 0; cc < 8; cc++) {
            int col = col0 + cc*4 + g;
            s[cc] = (col <= myrow) ? s[cc]*0.125f : -1e30f;
            mx = fmaxf(mx, s[cc]);
        }
        mx = fmaxf(mx, __shfl_xor_sync(0xffffffffu, mx, 1));
        mx = fmaxf(mx, __shfl_xor_sync(0xffffffffu, mx, 2));
        float m_new = fmaxf(m_r, mx);
        float lt = 0.f;
#pragma unroll
        for (int cc = 0; cc < 8; cc++) {
            float p = __expf(s[cc] - m_new);
            Ps[r*36 + cc*4 + g] = p;
            lt += p;
        }
        lt += __shfl_xor_sync(0xffffffffu, lt, 1);
        lt += __shfl_xor_sync(0xffffffffu, lt, 2);
        float alpha = __expf(m_r - m_new);
        m_r = m_new;
        l_r = l_r*alpha + lt;
#pragma unroll
        for (int i = 0; i < 16; i++) O[i] *= alpha;
        __syncwarp();

#pragma unroll
        for (int c = 0; c < 32; c++) {
            float p = Ps[r*36 + c];
            const float* vp = &Vs[c*68 + g*16];
            float4 v0 = *(const float4*)(vp + 0);
            float4 v1 = *(const float4*)(vp + 4);
            float4 v2 = *(const float4*)(vp + 8);
            float4 v3 = *(const float4*)(vp + 12);
            O[0]  = fmaf(p, v0.x, O[0]);  O[1]  = fmaf(p, v0.y, O[1]);
            O[2]  = fmaf(p, v0.z, O[2]);  O[3]  = fmaf(p, v0.w, O[3]);
            O[4]  = fmaf(p, v1.x, O[4]);  O[5]  = fmaf(p, v1.y, O[5]);
            O[6]  = fmaf(p, v1.z, O[6]);  O[7]  = fmaf(p, v1.w, O[7]);
            O[8]  = fmaf(p, v2.x, O[8]);  O[9]  = fmaf(p, v2.y, O[9]);
            O[10] = fmaf(p, v2.z, O[10]); O[11] = fmaf(p, v2.w, O[11]);
            O[12] = fmaf(p, v3.x, O[12]); O[13] = fmaf(p, v3.y, O[13]);
            O[14] = fmaf(p, v3.z, O[14]); O[15] = fmaf(p, v3.w, O[15]);
        }
        __syncthreads();
    }

    float inv = 1.0f / l_r;
    int h = bh & (HH - 1), bi = bh >> 4;
    float* yr = g_y + ((size_t)(bi*TT + myrow))*CC + h*DD + g*16;
#pragma unroll
    for (int i = 0; i < 16; i++) yr[i] = O[i]*inv;
}

// ---------------------------------------------------------------------------
extern "C" void kernel_launch(void* const* d_in, const int* in_sizes, int n_in,
                              void* d_out, int out_size) {
    const float* x  = (const float*)d_in[0];
    const float* aw = (const float*)d_in[1];
    const float* ab = (const float*)d_in[2];
    const float* aA = (const float*)d_in[3];
    const float* aB = (const float*)d_in[4];
    const float* pw = (const float*)d_in[5];
    const float* pb = (const float*)d_in[6];
    const float* pA = (const float*)d_in[7];
    const float* pB = (const float*)d_in[8];
    (void)in_sizes; (void)n_in; (void)out_size;

    float* out  = (float*)d_out;
    float* outQ = out + (size_t)MM*CC;
    float* outK = out + (size_t)2*MM*CC;

    const int SMEM_DYN = 2 * STAGE_BYTES + 1024;   // 129 KB
    cudaFuncSetAttribute(mma_gemm<0>, cudaFuncAttributeMaxDynamicSharedMemorySize, SMEM_DYN);
    cudaFuncSetAttribute(mma_gemm<1>, cudaFuncAttributeMaxDynamicSharedMemorySize, SMEM_DYN);

    // 1) bf16 hi/lo splits of x and c_attn_w
    conv_split<0,0><<<(MM*CC/4 + 255)/256, 256>>>(x, MM*CC/4);
    conv_split<0,1><<<(NQKV*CC/4 + 255)/256, 256>>>(aw, NQKV*CC/4);
    // 2) LoRA intermediate for c_attn
    lora_kernel<0><<<MM/8, 256>>>(x, aA);
    // 3) QKV GEMM (HMMA) + bias + LoRA, scatter q/k/v, emit query/key
    mma_gemm<0><<<dim3(NQKV/128, MM/128), 256, SMEM_DYN>>>(ab, aB, outQ, outK);
    // 4) Causal flash attention -> g_y
    flash_kernel<<<dim3(TT/64, BB*HH), 256>>>();
    // 5) bf16 splits of y and c_proj_w
    conv_split<1,0><<<(MM*CC/4 + 255)/256, 256>>>(nullptr, MM*CC/4);
    conv_split<0,1><<<(CC*CC/4 + 255)/256, 256>>>(pw, CC*CC/4);
    // 6) LoRA intermediate for c_proj
    lora_kernel<1><<<MM/8, 256>>>(nullptr, pA);
    // 7) proj GEMM (HMMA) + bias + LoRA -> out
    mma_gemm<1><<<dim3(CC/128, MM/128), 256, SMEM_DYN>>>(pb, pB, out, nullptr);
}

// round 6
// speedup vs baseline: 4.6521x; 3.3674x over previous
#include <cuda_runtime.h>
#include <cuda_bf16.h>
#include <cstdint>
#include <cstddef>

// Problem constants (fixed by the dataset)
#define BB 4
#define TT 2048
#define CC 1024
#define HH 16
#define DD 64
#define RR 8
#define MM (BB*TT)        // 8192
#define NQKV (3*CC)       // 3072

// Scratch (device globals -- no allocation allowed)
__device__ float g_y[(size_t)MM*CC];         // attention output [B,T,C]
__device__ float g_t[(size_t)MM*RR];         // LoRA intermediate x@A^T
// bf16 split buffers (A side reused for x then y; B side for attn W then proj W)
__device__ __nv_bfloat16 g_ah[(size_t)MM*CC];
__device__ __nv_bfloat16 g_al[(size_t)MM*CC];
__device__ __nv_bfloat16 g_bh[(size_t)NQKV*CC];
__device__ __nv_bfloat16 g_bl[(size_t)NQKV*CC];
// q/k/v in [B,H,T,D] as bf16 hi/lo split
__device__ __nv_bfloat16 g_qh[(size_t)BB*HH*TT*DD];
__device__ __nv_bfloat16 g_ql[(size_t)BB*HH*TT*DD];
__device__ __nv_bfloat16 g_kh[(size_t)BB*HH*TT*DD];
__device__ __nv_bfloat16 g_kl[(size_t)BB*HH*TT*DD];
__device__ __nv_bfloat16 g_vh[(size_t)BB*HH*TT*DD];
__device__ __nv_bfloat16 g_vl[(size_t)BB*HH*TT*DD];

// ---------------------------------------------------------------------------
// Helpers (base-target ISA only: cp.async / ldmatrix / mma.sync)
// ---------------------------------------------------------------------------
__device__ __forceinline__ uint32_t smem_u32(const void* p) {
    uint32_t a;
    asm("{ .reg .u64 t; cvta.to.shared.u64 t, %1; cvt.u32.u64 %0, t; }"
        : "=r"(a) : "l"(p));
    return a;
}
#define SWZ128(off) ((off) ^ (((off) >> 3) & 0x70))

#define CP_ASYNC16(dst, src) \
    asm volatile("cp.async.cg.shared.global [%0], [%1], 16;" :: "r"(dst), "l"(src))
#define CP_COMMIT() asm volatile("cp.async.commit_group;" ::: "memory")
#define CP_WAIT(n)  asm volatile("cp.async.wait_group %0;" :: "n"(n) : "memory")

#define LDSM_X4(r, a) \
    asm volatile("ldmatrix.sync.aligned.m8n8.x4.shared.b16 {%0,%1,%2,%3}, [%4];" \
                 : "=r"((r)[0]), "=r"((r)[1]), "=r"((r)[2]), "=r"((r)[3]) : "r"(a))
#define LDSM_X4_T(r, a) \
    asm volatile("ldmatrix.sync.aligned.m8n8.x4.trans.shared.b16 {%0,%1,%2,%3}, [%4];" \
                 : "=r"((r)[0]), "=r"((r)[1]), "=r"((r)[2]), "=r"((r)[3]) : "r"(a))

#define MMA16816(d, a, b0, b1) \
    asm volatile("mma.sync.aligned.m16n8k16.row.col.f32.bf16.bf16.f32 " \
                 "{%0,%1,%2,%3}, {%4,%5,%6,%7}, {%8,%9}, {%0,%1,%2,%3};" \
                 : "+f"((d)[0]), "+f"((d)[1]), "+f"((d)[2]), "+f"((d)[3]) \
                 : "r"((a)[0]), "r"((a)[1]), "r"((a)[2]), "r"((a)[3]), \
                   "r"(b0), "r"(b1))

// split a float pair into bf16 hi pair + bf16 lo (residual) pair
__device__ __forceinline__ void split_pair(float a, float b, uint32_t& hi, uint32_t& lo) {
    __nv_bfloat162 h = __floats2bfloat162_rn(a, b);
    float ra = a - __bfloat162float(h.x);
    float rb = b - __bfloat162float(h.y);
    __nv_bfloat162 l = __floats2bfloat162_rn(ra, rb);
    hi = *(uint32_t*)&h;
    lo = *(uint32_t*)&l;
}

// ---------------------------------------------------------------------------
// fp32 -> bf16 hi/lo split conversion (x / weights).
// DSTB=1: write g_bh/g_bl, else g_ah/g_al.
// ---------------------------------------------------------------------------
template<int DSTB>
__global__ void conv_split(const float* __restrict__ src, int n4) {
    int i = blockIdx.x * blockDim.x + threadIdx.x;
    if (i >= n4) return;
    float4 v = ((const float4*)src)[i];
    __nv_bfloat16* H = DSTB ? g_bh : g_ah;
    __nv_bfloat16* L = DSTB ? g_bl : g_al;
    uint32_t h0, l0, h1, l1;
    split_pair(v.x, v.y, h0, l0);
    split_pair(v.z, v.w, h1, l1);
    ((uint32_t*)H)[2*i]   = h0;
    ((uint32_t*)H)[2*i+1] = h1;
    ((uint32_t*)L)[2*i]   = l0;
    ((uint32_t*)L)[2*i+1] = l1;
}

// ---------------------------------------------------------------------------
// LoRA intermediate: t[m, r] = sum_k X[m,k] * A[r,k]   (one warp per row m)
// ---------------------------------------------------------------------------
template<int SRC>
__global__ void lora_kernel(const float* __restrict__ Xin, const float* __restrict__ A) {
    const float* X = (SRC == 1) ? g_y : Xin;
    int warp = (blockIdx.x * blockDim.x + threadIdx.x) >> 5;
    int lane = threadIdx.x & 31;
    const float* xr = X + (size_t)warp * CC;
    float acc[RR];
#pragma unroll
    for (int r = 0; r < RR; r++) acc[r] = 0.f;
    for (int k = lane; k < CC; k += 32) {
        float xv = xr[k];
#pragma unroll
        for (int r = 0; r < RR; r++) acc[r] = fmaf(xv, __ldg(&A[r*CC + k]), acc[r]);
    }
#pragma unroll
    for (int r = 0; r < RR; r++) {
        acc[r] += __shfl_xor_sync(0xffffffffu, acc[r], 16);
        acc[r] += __shfl_xor_sync(0xffffffffu, acc[r], 8);
        acc[r] += __shfl_xor_sync(0xffffffffu, acc[r], 4);
        acc[r] += __shfl_xor_sync(0xffffffffu, acc[r], 2);
        acc[r] += __shfl_xor_sync(0xffffffffu, acc[r], 1);
    }
    if (lane == 0) {
#pragma unroll
        for (int r = 0; r < RR; r++) g_t[(size_t)warp*RR + r] = acc[r];
    }
}

// ---------------------------------------------------------------------------
// bf16-split HMMA GEMM (mma.sync m16n8k16) + bias + rank-8 LoRA epilogue.
// CTA tile 128x128, 8 warps of 64x32. K chunks of 64, double-buffered cp.async.
// MODE 0: QKV -> q/k/v bf16 hi/lo scatter + query/key fp32 outputs.
// MODE 1: proj -> plain [M,C] fp32 output.
// ---------------------------------------------------------------------------
#define STAGE_BYTES 65536
#define OFF_AH 0
#define OFF_AL 16384
#define OFF_BH 32768
#define OFF_BL 49152

template<int MODE>
__global__ void __launch_bounds__(256) mma_gemm(const float* __restrict__ bias,
                                                const float* __restrict__ Blora,
                                                float* __restrict__ out0,
                                                float* __restrict__ out1)
{
    extern __shared__ char smem_raw[];
    uint32_t raw = smem_u32(smem_raw);
    uint32_t sb = (raw + 1023u) & ~1023u;

    int tid  = threadIdx.x;
    int wid  = tid >> 5, lane = tid & 31;
    int wm   = wid >> 2;
    int wn   = wid & 3;
    int bm = blockIdx.y * 128;
    int bn = blockIdx.x * 128;

    int lrow = tid >> 1;
    int lq   = (tid & 1) * 4;

    float acc[4][4][4];
#pragma unroll
    for (int i = 0; i < 4; i++)
#pragma unroll
        for (int j = 0; j < 4; j++)
#pragma unroll
            for (int c = 0; c < 4; c++) acc[i][j][c] = 0.f;

    auto load_chunk = [&](int stage, int k0) {
        uint32_t base = sb + stage * STAGE_BYTES;
        const __nv_bfloat16* srcs[4] = { g_ah, g_al, g_bh, g_bl };
#pragma unroll
        for (int t = 0; t < 4; t++) {
            int grow = (t < 2) ? (bm + lrow) : (bn + lrow);
            const __nv_bfloat16* sp = srcs[t] + (size_t)grow * CC + k0 + lq * 8;
#pragma unroll
            for (int j = 0; j < 4; j++) {
                uint32_t boff = SWZ128((uint32_t)(lrow * 128 + (lq + j) * 16));
                CP_ASYNC16(base + t * 16384 + boff, sp + j * 8);
            }
        }
        CP_COMMIT();
    };

    const int NCHUNK = CC / 64;
    load_chunk(0, 0);

    for (int ch = 0; ch < NCHUNK; ++ch) {
        if (ch + 1 < NCHUNK) {
            load_chunk((ch + 1) & 1, (ch + 1) * 64);
            CP_WAIT(1);
        } else {
            CP_WAIT(0);
        }
        __syncthreads();
        uint32_t base = sb + (ch & 1) * STAGE_BYTES;

#pragma unroll
        for (int ks = 0; ks < 4; ks++) {
            uint32_t ah[4][4], al[4][4];
#pragma unroll
            for (int ma = 0; ma < 4; ma++) {
                int row = wm * 64 + ma * 16 + (lane & 15);
                uint32_t kb = ks * 32 + ((lane >> 4) << 4);
                uint32_t off = SWZ128((uint32_t)(row * 128) + kb);
                LDSM_X4(ah[ma], base + OFF_AH + off);
                LDSM_X4(al[ma], base + OFF_AL + off);
            }
            uint32_t bh[2][4], bl[2][4];
#pragma unroll
            for (int nb = 0; nb < 2; nb++) {
                int row = wn * 32 + nb * 16 + (lane & 7) + ((lane >> 4) << 3);
                uint32_t kb = ks * 32 + (((lane >> 3) & 1) << 4);
                uint32_t off = SWZ128((uint32_t)(row * 128) + kb);
                LDSM_X4(bh[nb], base + OFF_BH + off);
                LDSM_X4(bl[nb], base + OFF_BL + off);
            }
#pragma unroll
            for (int ma = 0; ma < 4; ma++) {
#pragma unroll
                for (int na = 0; na < 4; na++) {
                    int nb = na >> 1, h = (na & 1) * 2;
                    MMA16816(acc[ma][na], ah[ma], bh[nb][h], bh[nb][h+1]);
                    MMA16816(acc[ma][na], ah[ma], bl[nb][h], bl[nb][h+1]);
                    MMA16816(acc[ma][na], al[ma], bh[nb][h], bh[nb][h+1]);
                }
            }
        }
        __syncthreads();
    }

    // ---- epilogue: + bias + LoRA, write out ----
#pragma unroll
    for (int ma = 0; ma < 4; ma++) {
        int m0 = bm + wm * 64 + ma * 16 + (lane >> 2);
        int m1 = m0 + 8;
        float4 t0a = *(const float4*)&g_t[(size_t)m0 * RR];
        float4 t0b = *(const float4*)&g_t[(size_t)m0 * RR + 4];
        float4 t1a = *(const float4*)&g_t[(size_t)m1 * RR];
        float4 t1b = *(const float4*)&g_t[(size_t)m1 * RR + 4];
#pragma unroll
        for (int na = 0; na < 4; na++) {
            int n0 = bn + wn * 32 + na * 8 + (lane & 3) * 2;
            int n1 = n0 + 1;
            float4 b0a = *(const float4*)&Blora[(size_t)n0 * RR];
            float4 b0b = *(const float4*)&Blora[(size_t)n0 * RR + 4];
            float4 b1a = *(const float4*)&Blora[(size_t)n1 * RR];
            float4 b1b = *(const float4*)&Blora[(size_t)n1 * RR + 4];
            float bs0 = __ldg(&bias[n0]), bs1 = __ldg(&bias[n1]);
            float v00 = acc[ma][na][0] + bs0
                + t0a.x*b0a.x + t0a.y*b0a.y + t0a.z*b0a.z + t0a.w*b0a.w
                + t0b.x*b0b.x + t0b.y*b0b.y + t0b.z*b0b.z + t0b.w*b0b.w;
            float v01 = acc[ma][na][1] + bs1
                + t0a.x*b1a.x + t0a.y*b1a.y + t0a.z*b1a.z + t0a.w*b1a.w
                + t0b.x*b1b.x + t0b.y*b1b.y + t0b.z*b1b.z + t0b.w*b1b.w;
            float v10 = acc[ma][na][2] + bs0
                + t1a.x*b0a.x + t1a.y*b0a.y + t1a.z*b0a.z + t1a.w*b0a.w
                + t1b.x*b0b.x + t1b.y*b0b.y + t1b.z*b0b.z + t1b.w*b0b.w;
            float v11 = acc[ma][na][3] + bs1
                + t1a.x*b1a.x + t1a.y*b1a.y + t1a.z*b1a.z + t1a.w*b1a.w
                + t1b.x*b1b.x + t1b.y*b1b.y + t1b.z*b1b.z + t1b.w*b1b.w;

            if (MODE == 0) {
                int sec = n0 >> 10;            // 0=q, 1=k, 2=v
                int cci = n0 & 1023;
                int h = cci >> 6, dd = cci & 63;
                __nv_bfloat16* dh = (sec == 0) ? g_qh : ((sec == 1) ? g_kh : g_vh);
                __nv_bfloat16* dl = (sec == 0) ? g_ql : ((sec == 1) ? g_kl : g_vl);
                {
                    int bi = m0 >> 11, ti = m0 & 2047;
                    size_t idx = ((size_t)((bi*HH) + h)*TT + ti)*DD + dd;
                    uint32_t hp, lp; split_pair(v00, v01, hp, lp);
                    *(uint32_t*)&dh[idx] = hp;
                    *(uint32_t*)&dl[idx] = lp;
                    float2 p; p.x = v00; p.y = v01;
                    if (sec == 0)      *(float2*)&out0[(size_t)m0*CC + cci] = p;
                    else if (sec == 1) *(float2*)&out1[(size_t)m0*CC + cci] = p;
                }
                {
                    int bi = m1 >> 11, ti = m1 & 2047;
                    size_t idx = ((size_t)((bi*HH) + h)*TT + ti)*DD + dd;
                    uint32_t hp, lp; split_pair(v10, v11, hp, lp);
                    *(uint32_t*)&dh[idx] = hp;
                    *(uint32_t*)&dl[idx] = lp;
                    float2 p; p.x = v10; p.y = v11;
                    if (sec == 0)      *(float2*)&out0[(size_t)m1*CC + cci] = p;
                    else if (sec == 1) *(float2*)&out1[(size_t)m1*CC + cci] = p;
                }
            } else {
                float2 p0; p0.x = v00; p0.y = v01;
                float2 p1; p1.x = v10; p1.y = v11;
                *(float2*)&out0[(size_t)m0*CC + n0] = p0;
                *(float2*)&out0[(size_t)m1*CC + n0] = p1;
            }
        }
    }
}

// ---------------------------------------------------------------------------
// Tensor-core causal flash attention (bf16 split, fp32 softmax).
// CTA: 64 Q-rows, 128 threads (4 warps x 16 rows). K/V tiles 64 x 64,
// hi/lo split, cp.async double-buffered. S frags reused as P frags.
// ---------------------------------------------------------------------------
#define FS_STAGE 32768
#define FS_KH 0
#define FS_KL 8192
#define FS_VH 16384
#define FS_VL 24576

__global__ void __launch_bounds__(128) flash_mma(float* __restrict__ dummy) {
    extern __shared__ char smem_raw[];
    uint32_t raw = smem_u32(smem_raw);
    uint32_t sb = (raw + 1023u) & ~1023u;

    int bh = blockIdx.y;
    int qi = gridDim.x - 1 - (int)blockIdx.x;   // long blocks first
    int tid = threadIdx.x;
    int wid = tid >> 5, lane = tid & 31;
    int row0 = qi * 64;

    const __nv_bfloat16* Qh = g_qh + ((size_t)bh*TT + row0) * DD;
    const __nv_bfloat16* Ql = g_ql + ((size_t)bh*TT + row0) * DD;
    const __nv_bfloat16* Kh = g_kh + (size_t)bh*TT*DD;
    const __nv_bfloat16* Kl = g_kl + (size_t)bh*TT*DD;
    const __nv_bfloat16* Vh = g_vh + (size_t)bh*TT*DD;
    const __nv_bfloat16* Vl = g_vl + (size_t)bh*TT*DD;

    auto load_tile = [&](uint32_t dst, const __nv_bfloat16* src) {
#pragma unroll
        for (int i = 0; i < 4; i++) {
            int e = tid + i * 128;
            int row = e >> 3, q = e & 7;
            CP_ASYNC16(dst + SWZ128((uint32_t)(row * 128 + q * 16)), src + row * 64 + q * 8);
        }
    };

    // ---- load Q into stage0 K area, move to registers ----
    load_tile(sb + FS_KH, Qh);
    load_tile(sb + FS_KL, Ql);
    CP_COMMIT();
    CP_WAIT(0);
    __syncthreads();
    uint32_t qh[4][4], ql[4][4];
#pragma unroll
    for (int k = 0; k < 4; k++) {
        int row = wid * 16 + (lane & 15);
        uint32_t kb = k * 32 + ((lane >> 4) << 4);
        uint32_t off = SWZ128((uint32_t)(row * 128) + kb);
        LDSM_X4(qh[k], sb + FS_KH + off);
        LDSM_X4(ql[k], sb + FS_KL + off);
    }
    __syncthreads();

    float oacc[8][4];
#pragma unroll
    for (int i = 0; i < 8; i++)
#pragma unroll
        for (int c = 0; c < 4; c++) oacc[i][c] = 0.f;
    float m_pr[2] = { -1e30f, -1e30f };
    float l_pr[2] = { 0.f, 0.f };

    int jmax = qi;
    auto load_kv = [&](int stage, int j) {
        uint32_t base = sb + stage * FS_STAGE;
        size_t o = (size_t)j * 64 * DD;
        load_tile(base + FS_KH, Kh + o);
        load_tile(base + FS_KL, Kl + o);
        load_tile(base + FS_VH, Vh + o);
        load_tile(base + FS_VL, Vl + o);
        CP_COMMIT();
    };
    load_kv(0, 0);

    for (int j = 0; j <= jmax; ++j) {
        if (j < jmax) { load_kv((j + 1) & 1, j + 1); CP_WAIT(1); }
        else          { CP_WAIT(0); }
        __syncthreads();
        uint32_t base = sb + (j & 1) * FS_STAGE;

        // ---- S = Q K^T (3-term split) ----
        // kh4/kl4 blocks: [0]=(keys 0-7, d 0-7) [1]=(keys 8-15, d 0-7)
        //                 [2]=(keys 0-7, d 8-15) [3]=(keys 8-15, d 8-15)
        // (b0,b1) must advance along k=d for fixed keys: pairs (0,2) and (1,3).
        float sacc[8][4];
#pragma unroll
        for (int i = 0; i < 8; i++)
#pragma unroll
            for (int c = 0; c < 4; c++) sacc[i][c] = 0.f;
#pragma unroll
        for (int k = 0; k < 4; k++) {
#pragma unroll
            for (int np = 0; np < 4; np++) {
                uint32_t kh4[4], kl4[4];
                int row = np * 16 + (lane & 7) + ((lane >> 3) & 1) * 8;
                uint32_t col = k * 32 + ((lane >> 4) << 4);
                uint32_t off = SWZ128((uint32_t)(row * 128) + col);
                LDSM_X4(kh4, base + FS_KH + off);
                LDSM_X4(kl4, base + FS_KL + off);
                MMA16816(sacc[2*np],   qh[k], kh4[0], kh4[2]);
                MMA16816(sacc[2*np],   qh[k], kl4[0], kl4[2]);
                MMA16816(sacc[2*np],   ql[k], kh4[0], kh4[2]);
                MMA16816(sacc[2*np+1], qh[k], kh4[1], kh4[3]);
                MMA16816(sacc[2*np+1], qh[k], kl4[1], kl4[3]);
                MMA16816(sacc[2*np+1], ql[k], kh4[1], kh4[3]);
            }
        }

        // ---- scale + causal mask + online softmax ----
        bool diag = (j == jmax);
        int rl0 = wid * 16 + (lane >> 2);      // row within 64-tile (half 0)
        float mx[2] = { -1e30f, -1e30f };
#pragma unroll
        for (int na = 0; na < 8; na++) {
#pragma unroll
            for (int c = 0; c < 4; c++) {
                float s = sacc[na][c] * 0.125f;
                if (diag) {
                    int colg = na * 8 + (lane & 3) * 2 + (c & 1);
                    int rowg = rl0 + ((c >> 1) << 3);
                    if (colg > rowg) s = -1e30f;
                }
                sacc[na][c] = s;
                int hsel = c >> 1;
                mx[hsel] = fmaxf(mx[hsel], s);
            }
        }
#pragma unroll
        for (int h = 0; h < 2; h++) {
            mx[h] = fmaxf(mx[h], __shfl_xor_sync(0xffffffffu, mx[h], 1));
            mx[h] = fmaxf(mx[h], __shfl_xor_sync(0xffffffffu, mx[h], 2));
        }
        float m_new[2], alpha[2], lsum[2] = { 0.f, 0.f };
#pragma unroll
        for (int h = 0; h < 2; h++) {
            m_new[h] = fmaxf(m_pr[h], mx[h]);
            alpha[h] = __expf(m_pr[h] - m_new[h]);
            m_pr[h] = m_new[h];
        }
#pragma unroll
        for (int na = 0; na < 8; na++) {
#pragma unroll
            for (int c = 0; c < 4; c++) {
                int hsel = c >> 1;
                float p = __expf(sacc[na][c] - m_new[hsel]);
                sacc[na][c] = p;
                lsum[hsel] += p;
            }
        }
#pragma unroll
        for (int h = 0; h < 2; h++) {
            lsum[h] += __shfl_xor_sync(0xffffffffu, lsum[h], 1);
            lsum[h] += __shfl_xor_sync(0xffffffffu, lsum[h], 2);
            l_pr[h] = l_pr[h] * alpha[h] + lsum[h];
        }
#pragma unroll
        for (int na = 0; na < 8; na++) {
            oacc[na][0] *= alpha[0]; oacc[na][1] *= alpha[0];
            oacc[na][2] *= alpha[1]; oacc[na][3] *= alpha[1];
        }

        // ---- O += P V (3-term split; P frags packed from S accumulators) ----
        // vh4/vl4 (trans): [0]=(k 0-7, d 0-7) [1]=(k 8-15, d 0-7)
        //                  [2]=(k 0-7, d 8-15) [3]=(k 8-15, d 8-15)
        // here k = keys = rows, so (b0,b1) pairs are (0,1) and (2,3). (correct as-is)
#pragma unroll
        for (int s = 0; s < 4; s++) {
            uint32_t ph[4], pl[4];
            split_pair(sacc[2*s][0],   sacc[2*s][1],   ph[0], pl[0]);
            split_pair(sacc[2*s][2],   sacc[2*s][3],   ph[1], pl[1]);
            split_pair(sacc[2*s+1][0], sacc[2*s+1][1], ph[2], pl[2]);
            split_pair(sacc[2*s+1][2], sacc[2*s+1][3], ph[3], pl[3]);
#pragma unroll
            for (int np = 0; np < 4; np++) {
                uint32_t vh4[4], vl4[4];
                int row = s * 16 + (lane & 7) + ((lane >> 3) & 1) * 8;
                uint32_t col = np * 32 + ((lane >> 4) << 4);
                uint32_t off = SWZ128((uint32_t)(row * 128) + col);
                LDSM_X4_T(vh4, base + FS_VH + off);
                LDSM_X4_T(vl4, base + FS_VL + off);
                MMA16816(oacc[2*np],   ph, vh4[0], vh4[1]);
                MMA16816(oacc[2*np],   ph, vl4[0], vl4[1]);
                MMA16816(oacc[2*np],   pl, vh4[0], vh4[1]);
                MMA16816(oacc[2*np+1], ph, vh4[2], vh4[3]);
                MMA16816(oacc[2*np+1], ph, vl4[2], vl4[3]);
                MMA16816(oacc[2*np+1], pl, vh4[2], vh4[3]);
            }
        }
        __syncthreads();
    }

    // ---- epilogue: normalize, write fp32 g_y + bf16 split g_ah/g_al ----
    float inv0 = 1.0f / l_pr[0];
    float inv1 = 1.0f / l_pr[1];
    int h = bh & (HH - 1), bi = bh >> 4;
    int t0 = row0 + wid * 16 + (lane >> 2);
    int t1 = t0 + 8;
    int dbase = h * DD + (lane & 3) * 2;
#pragma unroll
    for (int na = 0; na < 8; na++) {
        int d = dbase + na * 8;
        size_t i0 = ((size_t)(bi*TT + t0))*CC + d;
        size_t i1 = ((size_t)(bi*TT + t1))*CC + d;
        float v00 = oacc[na][0]*inv0, v01 = oacc[na][1]*inv0;
        float v10 = oacc[na][2]*inv1, v11 = oacc[na][3]*inv1;
        float2 p0; p0.x = v00; p0.y = v01;
        float2 p1; p1.x = v10; p1.y = v11;
        *(float2*)&g_y[i0] = p0;
        *(float2*)&g_y[i1] = p1;
        uint32_t hp, lp;
        split_pair(v00, v01, hp, lp);
        *(uint32_t*)&g_ah[i0] = hp; *(uint32_t*)&g_al[i0] = lp;
        split_pair(v10, v11, hp, lp);
        *(uint32_t*)&g_ah[i1] = hp; *(uint32_t*)&g_al[i1] = lp;
    }
    (void)dummy;
}

// ---------------------------------------------------------------------------
extern "C" void kernel_launch(void* const* d_in, const int* in_sizes, int n_in,
                              void* d_out, int out_size) {
    const float* x  = (const float*)d_in[0];
    const float* aw = (const float*)d_in[1];
    const float* ab = (const float*)d_in[2];
    const float* aA = (const float*)d_in[3];
    const float* aB = (const float*)d_in[4];
    const float* pw = (const float*)d_in[5];
    const float* pb = (const float*)d_in[6];
    const float* pA = (const float*)d_in[7];
    const float* pB = (const float*)d_in[8];
    (void)in_sizes; (void)n_in; (void)out_size;

    float* out  = (float*)d_out;
    float* outQ = out + (size_t)MM*CC;
    float* outK = out + (size_t)2*MM*CC;

    const int SMEM_GEMM = 2 * STAGE_BYTES + 1024;   // 129 KB
    const int SMEM_FLASH = 2 * FS_STAGE + 1024;     // 65 KB
    cudaFuncSetAttribute(mma_gemm<0>, cudaFuncAttributeMaxDynamicSharedMemorySize, SMEM_GEMM);
    cudaFuncSetAttribute(mma_gemm<1>, cudaFuncAttributeMaxDynamicSharedMemorySize, SMEM_GEMM);
    cudaFuncSetAttribute(flash_mma, cudaFuncAttributeMaxDynamicSharedMemorySize, SMEM_FLASH);

    // 1) bf16 hi/lo splits of x and c_attn_w
    conv_split<0><<<(MM*CC/4 + 255)/256, 256>>>(x, MM*CC/4);
    conv_split<1><<<(NQKV*CC/4 + 255)/256, 256>>>(aw, NQKV*CC/4);
    // 2) LoRA intermediate for c_attn
    lora_kernel<0><<<MM/8, 256>>>(x, aA);
    // 3) QKV GEMM (HMMA): q/k/v bf16-split scatter + query/key outputs
    mma_gemm<0><<<dim3(NQKV/128, MM/128), 256, SMEM_GEMM>>>(ab, aB, outQ, outK);
    // 4) Tensor-core causal flash attention -> g_y (+ bf16 split g_ah/g_al)
    flash_mma<<<dim3(TT/64, BB*HH), 128, SMEM_FLASH>>>(nullptr);
    // 5) bf16 split of c_proj_w
    conv_split<1><<<(CC*CC/4 + 255)/256, 256>>>(pw, CC*CC/4);
    // 6) LoRA intermediate for c_proj
    lora_kernel<1><<<MM/8, 256>>>(nullptr, pA);
    // 7) proj GEMM (HMMA) + bias + LoRA -> out
    mma_gemm<1><<<dim3(CC/128, MM/128), 256, SMEM_GEMM>>>(pb, pB, out, nullptr);
}

// round 9
// speedup vs baseline: 4.7062x; 1.0116x over previous
#include <cuda_runtime.h>
#include <cuda_bf16.h>
#include <cstdint>
#include <cstddef>

// Problem constants (fixed by the dataset)
#define BB 4
#define TT 2048
#define CC 1024
#define HH 16
#define DD 64
#define RR 8
#define MM (BB*TT)        // 8192
#define NQKV (3*CC)       // 3072

// Scratch (device globals -- no allocation allowed).
// NOTE: these are referenced ONLY from device code (host code cannot take
// their address without cudaGetSymbolAddress -- that was the R7/R8 bug).
__device__ float g_y[(size_t)MM*CC];         // attention output [B,T,C]
__device__ float g_t[(size_t)MM*RR];         // LoRA intermediate x@A^T
__device__ __nv_bfloat16 g_ah[(size_t)MM*CC];     // x, then attention y (hi)
__device__ __nv_bfloat16 g_al[(size_t)MM*CC];     // (lo)
__device__ __nv_bfloat16 g_bh[(size_t)NQKV*CC];   // c_attn_w hi
__device__ __nv_bfloat16 g_bl[(size_t)NQKV*CC];   // c_attn_w lo
__device__ __nv_bfloat16 g_pwh[(size_t)CC*CC];    // c_proj_w hi
__device__ __nv_bfloat16 g_pwl[(size_t)CC*CC];    // c_proj_w lo
// q/k/v in [B,H,T,D] as bf16 hi/lo split
__device__ __nv_bfloat16 g_qh[(size_t)BB*HH*TT*DD];
__device__ __nv_bfloat16 g_ql[(size_t)BB*HH*TT*DD];
__device__ __nv_bfloat16 g_kh[(size_t)BB*HH*TT*DD];
__device__ __nv_bfloat16 g_kl[(size_t)BB*HH*TT*DD];
__device__ __nv_bfloat16 g_vh[(size_t)BB*HH*TT*DD];
__device__ __nv_bfloat16 g_vl[(size_t)BB*HH*TT*DD];

// ---------------------------------------------------------------------------
// Helpers (base-target ISA only: cp.async / ldmatrix / mma.sync)
// ---------------------------------------------------------------------------
__device__ __forceinline__ uint32_t smem_u32(const void* p) {
    uint32_t a;
    asm("{ .reg .u64 t; cvta.to.shared.u64 t, %1; cvt.u32.u64 %0, t; }"
        : "=r"(a) : "l"(p));
    return a;
}
#define SWZ128(off) ((off) ^ (((off) >> 3) & 0x70))

#define CP_ASYNC16(dst, src) \
    asm volatile("cp.async.cg.shared.global [%0], [%1], 16;" :: "r"(dst), "l"(src))
#define CP_COMMIT() asm volatile("cp.async.commit_group;" ::: "memory")
#define CP_WAIT(n)  asm volatile("cp.async.wait_group %0;" :: "n"(n) : "memory")

#define LDSM_X4(r, a) \
    asm volatile("ldmatrix.sync.aligned.m8n8.x4.shared.b16 {%0,%1,%2,%3}, [%4];" \
                 : "=r"((r)[0]), "=r"((r)[1]), "=r"((r)[2]), "=r"((r)[3]) : "r"(a))
#define LDSM_X4_T(r, a) \
    asm volatile("ldmatrix.sync.aligned.m8n8.x4.trans.shared.b16 {%0,%1,%2,%3}, [%4];" \
                 : "=r"((r)[0]), "=r"((r)[1]), "=r"((r)[2]), "=r"((r)[3]) : "r"(a))

#define MMA16816(d, a, b0, b1) \
    asm volatile("mma.sync.aligned.m16n8k16.row.col.f32.bf16.bf16.f32 " \
                 "{%0,%1,%2,%3}, {%4,%5,%6,%7}, {%8,%9}, {%0,%1,%2,%3};" \
                 : "+f"((d)[0]), "+f"((d)[1]), "+f"((d)[2]), "+f"((d)[3]) \
                 : "r"((a)[0]), "r"((a)[1]), "r"((a)[2]), "r"((a)[3]), \
                   "r"(b0), "r"(b1))

// split a float pair into bf16 hi pair + bf16 lo (residual) pair
__device__ __forceinline__ void split_pair(float a, float b, uint32_t& hi, uint32_t& lo) {
    __nv_bfloat162 h = __floats2bfloat162_rn(a, b);
    float ra = a - __bfloat162float(h.x);
    float rb = b - __bfloat162float(h.y);
    __nv_bfloat162 l = __floats2bfloat162_rn(ra, rb);
    hi = *(uint32_t*)&h;
    lo = *(uint32_t*)&l;
}

// ---------------------------------------------------------------------------
// fp32 -> bf16 hi/lo split conversion. DST selects device-global target
// INSIDE device code: 0 -> g_ah/g_al, 1 -> g_bh/g_bl, 2 -> g_pwh/g_pwl.
// ---------------------------------------------------------------------------
template<int DST>
__global__ void conv_split(const float* __restrict__ src, int n4) {
    int i = blockIdx.x * blockDim.x + threadIdx.x;
    if (i >= n4) return;
    float4 v = ((const float4*)src)[i];
    __nv_bfloat16* H = (DST == 0) ? g_ah : ((DST == 1) ? g_bh : g_pwh);
    __nv_bfloat16* L = (DST == 0) ? g_al : ((DST == 1) ? g_bl : g_pwl);
    uint32_t h0, l0, h1, l1;
    split_pair(v.x, v.y, h0, l0);
    split_pair(v.z, v.w, h1, l1);
    ((uint32_t*)H)[2*i]   = h0;
    ((uint32_t*)H)[2*i+1] = h1;
    ((uint32_t*)L)[2*i]   = l0;
    ((uint32_t*)L)[2*i+1] = l1;
}

// ---------------------------------------------------------------------------
// LoRA intermediate: t[m, r] = sum_k X[m,k] * A[r,k]   (one warp per row m)
// ---------------------------------------------------------------------------
template<int SRC>
__global__ void lora_kernel(const float* __restrict__ Xin, const float* __restrict__ A) {
    const float* X = (SRC == 1) ? g_y : Xin;
    int warp = (blockIdx.x * blockDim.x + threadIdx.x) >> 5;
    int lane = threadIdx.x & 31;
    const float* xr = X + (size_t)warp * CC;
    float acc[RR];
#pragma unroll
    for (int r = 0; r < RR; r++) acc[r] = 0.f;
    for (int k = lane; k < CC; k += 32) {
        float xv = xr[k];
#pragma unroll
        for (int r = 0; r < RR; r++) acc[r] = fmaf(xv, __ldg(&A[r*CC + k]), acc[r]);
    }
#pragma unroll
    for (int r = 0; r < RR; r++) {
        acc[r] += __shfl_xor_sync(0xffffffffu, acc[r], 16);
        acc[r] += __shfl_xor_sync(0xffffffffu, acc[r], 8);
        acc[r] += __shfl_xor_sync(0xffffffffu, acc[r], 4);
        acc[r] += __shfl_xor_sync(0xffffffffu, acc[r], 2);
        acc[r] += __shfl_xor_sync(0xffffffffu, acc[r], 1);
    }
    if (lane == 0) {
#pragma unroll
        for (int r = 0; r < RR; r++) g_t[(size_t)warp*RR + r] = acc[r];
    }
}

// ---------------------------------------------------------------------------
// bf16-split HMMA GEMM (mma.sync m16n8k16) + bias + rank-8 LoRA epilogue.
// CTA tile 128x128, 128 threads: 4 warps in 2x2, each warp 64x64.
// (64x64 warp tile: 85 B smem-read per MMA vs 128 at 64x32.)
// K chunks of 64, double-buffered cp.async, stage = 64KB, smem 129KB.
// MODE 0: QKV (weights g_bh/g_bl) -> q/k/v hi/lo scatter + query/key outs.
// MODE 1: proj (weights g_pwh/g_pwl) -> plain [M,C] fp32 output.
// ---------------------------------------------------------------------------
#define STAGE_BYTES 65536
#define OFF_AH 0
#define OFF_AL 16384
#define OFF_BH 32768
#define OFF_BL 49152

template<int MODE>
__global__ void __launch_bounds__(128) mma_gemm(const float* __restrict__ bias,
                                                const float* __restrict__ Blora,
                                                float* __restrict__ out0,
                                                float* __restrict__ out1)
{
    extern __shared__ char smem_raw[];
    uint32_t raw = smem_u32(smem_raw);
    uint32_t sb = (raw + 1023u) & ~1023u;

    const __nv_bfloat16* Wh = (MODE == 0) ? g_bh : g_pwh;   // device-side select
    const __nv_bfloat16* Wl = (MODE == 0) ? g_bl : g_pwl;

    int tid  = threadIdx.x;
    int wid  = tid >> 5, lane = tid & 31;
    int wm   = wid >> 1;       // 0..1 -> 64-row slab
    int wn   = wid & 1;        // 0..1 -> 64-col slab
    int bm = blockIdx.y * 128;
    int bn = blockIdx.x * 128;

    int lrow2 = tid >> 1;      // 0..63 (2 threads per row)
    int lq4   = (tid & 1) * 4; // uint4 index within row (0 or 4)

    float acc[4][8][4];
#pragma unroll
    for (int i = 0; i < 4; i++)
#pragma unroll
        for (int j = 0; j < 8; j++)
#pragma unroll
            for (int c = 0; c < 4; c++) acc[i][j][c] = 0.f;

    auto load_chunk = [&](int stage, int k0) {
        uint32_t base = sb + stage * STAGE_BYTES;
#pragma unroll
        for (int i = 0; i < 2; i++) {
            int row = lrow2 + i * 64;
            size_t goA = (size_t)(bm + row) * CC + k0 + lq4 * 8;
            size_t goB = (size_t)(bn + row) * CC + k0 + lq4 * 8;
#pragma unroll
            for (int j = 0; j < 4; j++) {
                uint32_t boff = SWZ128((uint32_t)(row * 128 + (lq4 + j) * 16));
                CP_ASYNC16(base + OFF_AH + boff, g_ah + goA + j * 8);
                CP_ASYNC16(base + OFF_AL + boff, g_al + goA + j * 8);
                CP_ASYNC16(base + OFF_BH + boff, Wh + goB + j * 8);
                CP_ASYNC16(base + OFF_BL + boff, Wl + goB + j * 8);
            }
        }
        CP_COMMIT();
    };

    const int NCHUNK = CC / 64;
    load_chunk(0, 0);

    for (int ch = 0; ch < NCHUNK; ++ch) {
        if (ch + 1 < NCHUNK) {
            load_chunk((ch + 1) & 1, (ch + 1) * 64);
            CP_WAIT(1);
        } else {
            CP_WAIT(0);
        }
        __syncthreads();
        uint32_t base = sb + (ch & 1) * STAGE_BYTES;

#pragma unroll
        for (int ks = 0; ks < 4; ks++) {
            uint32_t ah[4][4], al[4][4];
#pragma unroll
            for (int ma = 0; ma < 4; ma++) {
                int row = wm * 64 + ma * 16 + (lane & 15);
                uint32_t kb = ks * 32 + ((lane >> 4) << 4);
                uint32_t off = SWZ128((uint32_t)(row * 128) + kb);
                LDSM_X4(ah[ma], base + OFF_AH + off);
                LDSM_X4(al[ma], base + OFF_AL + off);
            }
#pragma unroll
            for (int nb = 0; nb < 4; nb++) {
                uint32_t bh4[4], bl4[4];
                int row = wn * 64 + nb * 16 + (lane & 7) + ((lane >> 4) << 3);
                uint32_t kb = ks * 32 + (((lane >> 3) & 1) << 4);
                uint32_t off = SWZ128((uint32_t)(row * 128) + kb);
                LDSM_X4(bh4, base + OFF_BH + off);
                LDSM_X4(bl4, base + OFF_BL + off);
#pragma unroll
                for (int ma = 0; ma < 4; ma++) {
#pragma unroll
                    for (int h = 0; h < 2; h++) {
                        float* d = acc[ma][nb * 2 + h];
                        MMA16816(d, ah[ma], bh4[2*h], bh4[2*h+1]);
                        MMA16816(d, ah[ma], bl4[2*h], bl4[2*h+1]);
                        MMA16816(d, al[ma], bh4[2*h], bh4[2*h+1]);
                    }
                }
            }
        }
        __syncthreads();
    }

    // ---- epilogue: + bias + LoRA, write out ----
#pragma unroll
    for (int ma = 0; ma < 4; ma++) {
        int m0 = bm + wm * 64 + ma * 16 + (lane >> 2);
        int m1 = m0 + 8;
        float4 t0a = *(const float4*)&g_t[(size_t)m0 * RR];
        float4 t0b = *(const float4*)&g_t[(size_t)m0 * RR + 4];
        float4 t1a = *(const float4*)&g_t[(size_t)m1 * RR];
        float4 t1b = *(const float4*)&g_t[(size_t)m1 * RR + 4];
#pragma unroll
        for (int na = 0; na < 8; na++) {
            int n0 = bn + wn * 64 + na * 8 + (lane & 3) * 2;
            int n1 = n0 + 1;
            float4 b0a = *(const float4*)&Blora[(size_t)n0 * RR];
            float4 b0b = *(const float4*)&Blora[(size_t)n0 * RR + 4];
            float4 b1a = *(const float4*)&Blora[(size_t)n1 * RR];
            float4 b1b = *(const float4*)&Blora[(size_t)n1 * RR + 4];
            float bs0 = __ldg(&bias[n0]), bs1 = __ldg(&bias[n1]);
            float v00 = acc[ma][na][0] + bs0
                + t0a.x*b0a.x + t0a.y*b0a.y + t0a.z*b0a.z + t0a.w*b0a.w
                + t0b.x*b0b.x + t0b.y*b0b.y + t0b.z*b0b.z + t0b.w*b0b.w;
            float v01 = acc[ma][na][1] + bs1
                + t0a.x*b1a.x + t0a.y*b1a.y + t0a.z*b1a.z + t0a.w*b1a.w
                + t0b.x*b1b.x + t0b.y*b1b.y + t0b.z*b1b.z + t0b.w*b1b.w;
            float v10 = acc[ma][na][2] + bs0
                + t1a.x*b0a.x + t1a.y*b0a.y + t1a.z*b0a.z + t1a.w*b0a.w
                + t1b.x*b0b.x + t1b.y*b0b.y + t1b.z*b0b.z + t1b.w*b0b.w;
            float v11 = acc[ma][na][3] + bs1
                + t1a.x*b1a.x + t1a.y*b1a.y + t1a.z*b1a.z + t1a.w*b1a.w
                + t1b.x*b1b.x + t1b.y*b1b.y + t1b.z*b1b.z + t1b.w*b1b.w;

            if (MODE == 0) {
                int sec = n0 >> 10;            // 0=q, 1=k, 2=v
                int cci = n0 & 1023;
                int h = cci >> 6, dd = cci & 63;
                __nv_bfloat16* dh = (sec == 0) ? g_qh : ((sec == 1) ? g_kh : g_vh);
                __nv_bfloat16* dl = (sec == 0) ? g_ql : ((sec == 1) ? g_kl : g_vl);
                {
                    int bi = m0 >> 11, ti = m0 & 2047;
                    size_t idx = ((size_t)((bi*HH) + h)*TT + ti)*DD + dd;
                    uint32_t hp, lp; split_pair(v00, v01, hp, lp);
                    *(uint32_t*)&dh[idx] = hp;
                    *(uint32_t*)&dl[idx] = lp;
                    float2 p; p.x = v00; p.y = v01;
                    if (sec == 0)      *(float2*)&out0[(size_t)m0*CC + cci] = p;
                    else if (sec == 1) *(float2*)&out1[(size_t)m0*CC + cci] = p;
                }
                {
                    int bi = m1 >> 11, ti = m1 & 2047;
                    size_t idx = ((size_t)((bi*HH) + h)*TT + ti)*DD + dd;
                    uint32_t hp, lp; split_pair(v10, v11, hp, lp);
                    *(uint32_t*)&dh[idx] = hp;
                    *(uint32_t*)&dl[idx] = lp;
                    float2 p; p.x = v10; p.y = v11;
                    if (sec == 0)      *(float2*)&out0[(size_t)m1*CC + cci] = p;
                    else if (sec == 1) *(float2*)&out1[(size_t)m1*CC + cci] = p;
                }
            } else {
                float2 p0; p0.x = v00; p0.y = v01;
                float2 p1; p1.x = v10; p1.y = v11;
                *(float2*)&out0[(size_t)m0*CC + n0] = p0;
                *(float2*)&out0[(size_t)m1*CC + n0] = p1;
            }
        }
    }
}

// ---------------------------------------------------------------------------
// Tensor-core causal flash attention (bf16 split, fp32 softmax).
// CTA: 64 Q-rows, 128 threads (4 warps x 16 rows). K/V tiles 64 x 64,
// hi/lo split, cp.async double-buffered. S frags reused as P frags.
// ---------------------------------------------------------------------------
#define FS_STAGE 32768
#define FS_KH 0
#define FS_KL 8192
#define FS_VH 16384
#define FS_VL 24576

__global__ void __launch_bounds__(128) flash_mma(float* __restrict__ dummy) {
    extern __shared__ char smem_raw[];
    uint32_t raw = smem_u32(smem_raw);
    uint32_t sb = (raw + 1023u) & ~1023u;

    int bh = blockIdx.y;
    int qi = gridDim.x - 1 - (int)blockIdx.x;   // long blocks first
    int tid = threadIdx.x;
    int wid = tid >> 5, lane = tid & 31;
    int row0 = qi * 64;

    const __nv_bfloat16* Qh = g_qh + ((size_t)bh*TT + row0) * DD;
    const __nv_bfloat16* Ql = g_ql + ((size_t)bh*TT + row0) * DD;
    const __nv_bfloat16* Kh = g_kh + (size_t)bh*TT*DD;
    const __nv_bfloat16* Kl = g_kl + (size_t)bh*TT*DD;
    const __nv_bfloat16* Vh = g_vh + (size_t)bh*TT*DD;
    const __nv_bfloat16* Vl = g_vl + (size_t)bh*TT*DD;

    auto load_tile = [&](uint32_t dst, const __nv_bfloat16* src) {
#pragma unroll
        for (int i = 0; i < 4; i++) {
            int e = tid + i * 128;
            int row = e >> 3, q = e & 7;
            CP_ASYNC16(dst + SWZ128((uint32_t)(row * 128 + q * 16)), src + row * 64 + q * 8);
        }
    };

    // ---- load Q into stage0 K area, move to registers ----
    load_tile(sb + FS_KH, Qh);
    load_tile(sb + FS_KL, Ql);
    CP_COMMIT();
    CP_WAIT(0);
    __syncthreads();
    uint32_t qh[4][4], ql[4][4];
#pragma unroll
    for (int k = 0; k < 4; k++) {
        int row = wid * 16 + (lane & 15);
        uint32_t kb = k * 32 + ((lane >> 4) << 4);
        uint32_t off = SWZ128((uint32_t)(row * 128) + kb);
        LDSM_X4(qh[k], sb + FS_KH + off);
        LDSM_X4(ql[k], sb + FS_KL + off);
    }
    __syncthreads();

    float oacc[8][4];
#pragma unroll
    for (int i = 0; i < 8; i++)
#pragma unroll
        for (int c = 0; c < 4; c++) oacc[i][c] = 0.f;
    float m_pr[2] = { -1e30f, -1e30f };
    float l_pr[2] = { 0.f, 0.f };

    int jmax = qi;
    auto load_kv = [&](int stage, int j) {
        uint32_t base = sb + stage * FS_STAGE;
        size_t o = (size_t)j * 64 * DD;
        load_tile(base + FS_KH, Kh + o);
        load_tile(base + FS_KL, Kl + o);
        load_tile(base + FS_VH, Vh + o);
        load_tile(base + FS_VL, Vl + o);
        CP_COMMIT();
    };
    load_kv(0, 0);

    for (int j = 0; j <= jmax; ++j) {
        if (j < jmax) { load_kv((j + 1) & 1, j + 1); CP_WAIT(1); }
        else          { CP_WAIT(0); }
        __syncthreads();
        uint32_t base = sb + (j & 1) * FS_STAGE;

        // ---- S = Q K^T (3-term split) ----
        float sacc[8][4];
#pragma unroll
        for (int i = 0; i < 8; i++)
#pragma unroll
            for (int c = 0; c < 4; c++) sacc[i][c] = 0.f;
#pragma unroll
        for (int k = 0; k < 4; k++) {
#pragma unroll
            for (int np = 0; np < 4; np++) {
                uint32_t kh4[4], kl4[4];
                int row = np * 16 + (lane & 7) + ((lane >> 3) & 1) * 8;
                uint32_t col = k * 32 + ((lane >> 4) << 4);
                uint32_t off = SWZ128((uint32_t)(row * 128) + col);
                LDSM_X4(kh4, base + FS_KH + off);
                LDSM_X4(kl4, base + FS_KL + off);
                MMA16816(sacc[2*np],   qh[k], kh4[0], kh4[2]);
                MMA16816(sacc[2*np],   qh[k], kl4[0], kl4[2]);
                MMA16816(sacc[2*np],   ql[k], kh4[0], kh4[2]);
                MMA16816(sacc[2*np+1], qh[k], kh4[1], kh4[3]);
                MMA16816(sacc[2*np+1], qh[k], kl4[1], kl4[3]);
                MMA16816(sacc[2*np+1], ql[k], kh4[1], kh4[3]);
            }
        }

        // ---- scale + causal mask + online softmax ----
        bool diag = (j == jmax);
        int rl0 = wid * 16 + (lane >> 2);
        float mx[2] = { -1e30f, -1e30f };
#pragma unroll
        for (int na = 0; na < 8; na++) {
#pragma unroll
            for (int c = 0; c < 4; c++) {
                float s = sacc[na][c] * 0.125f;
                if (diag) {
                    int colg = na * 8 + (lane & 3) * 2 + (c & 1);
                    int rowg = rl0 + ((c >> 1) << 3);
                    if (colg > rowg) s = -1e30f;
                }
                sacc[na][c] = s;
                int hsel = c >> 1;
                mx[hsel] = fmaxf(mx[hsel], s);
            }
        }
#pragma unroll
        for (int h = 0; h < 2; h++) {
            mx[h] = fmaxf(mx[h], __shfl_xor_sync(0xffffffffu, mx[h], 1));
            mx[h] = fmaxf(mx[h], __shfl_xor_sync(0xffffffffu, mx[h], 2));
        }
        float m_new[2], alpha[2], lsum[2] = { 0.f, 0.f };
#pragma unroll
        for (int h = 0; h < 2; h++) {
            m_new[h] = fmaxf(m_pr[h], mx[h]);
            alpha[h] = __expf(m_pr[h] - m_new[h]);
            m_pr[h] = m_new[h];
        }
#pragma unroll
        for (int na = 0; na < 8; na++) {
#pragma unroll
            for (int c = 0; c < 4; c++) {
                int hsel = c >> 1;
                float p = __expf(sacc[na][c] - m_new[hsel]);
                sacc[na][c] = p;
                lsum[hsel] += p;
            }
        }
#pragma unroll
        for (int h = 0; h < 2; h++) {
            lsum[h] += __shfl_xor_sync(0xffffffffu, lsum[h], 1);
            lsum[h] += __shfl_xor_sync(0xffffffffu, lsum[h], 2);
            l_pr[h] = l_pr[h] * alpha[h] + lsum[h];
        }
#pragma unroll
        for (int na = 0; na < 8; na++) {
            oacc[na][0] *= alpha[0]; oacc[na][1] *= alpha[0];
            oacc[na][2] *= alpha[1]; oacc[na][3] *= alpha[1];
        }

        // ---- O += P V (3-term split) ----
#pragma unroll
        for (int s = 0; s < 4; s++) {
            uint32_t ph[4], pl[4];
            split_pair(sacc[2*s][0],   sacc[2*s][1],   ph[0], pl[0]);
            split_pair(sacc[2*s][2],   sacc[2*s][3],   ph[1], pl[1]);
            split_pair(sacc[2*s+1][0], sacc[2*s+1][1], ph[2], pl[2]);
            split_pair(sacc[2*s+1][2], sacc[2*s+1][3], ph[3], pl[3]);
#pragma unroll
            for (int np = 0; np < 4; np++) {
                uint32_t vh4[4], vl4[4];
                int row = s * 16 + (lane & 7) + ((lane >> 3) & 1) * 8;
                uint32_t col = np * 32 + ((lane >> 4) << 4);
                uint32_t off = SWZ128((uint32_t)(row * 128) + col);
                LDSM_X4_T(vh4, base + FS_VH + off);
                LDSM_X4_T(vl4, base + FS_VL + off);
                MMA16816(oacc[2*np],   ph, vh4[0], vh4[1]);
                MMA16816(oacc[2*np],   ph, vl4[0], vl4[1]);
                MMA16816(oacc[2*np],   pl, vh4[0], vh4[1]);
                MMA16816(oacc[2*np+1], ph, vh4[2], vh4[3]);
                MMA16816(oacc[2*np+1], ph, vl4[2], vl4[3]);
                MMA16816(oacc[2*np+1], pl, vh4[2], vh4[3]);
            }
        }
        __syncthreads();
    }

    // ---- epilogue: normalize, write fp32 g_y + bf16 split g_ah/g_al ----
    float inv0 = 1.0f / l_pr[0];
    float inv1 = 1.0f / l_pr[1];
    int h = bh & (HH - 1), bi = bh >> 4;
    int t0 = row0 + wid * 16 + (lane >> 2);
    int t1 = t0 + 8;
    int dbase = h * DD + (lane & 3) * 2;
#pragma unroll
    for (int na = 0; na < 8; na++) {
        int d = dbase + na * 8;
        size_t i0 = ((size_t)(bi*TT + t0))*CC + d;
        size_t i1 = ((size_t)(bi*TT + t1))*CC + d;
        float v00 = oacc[na][0]*inv0, v01 = oacc[na][1]*inv0;
        float v10 = oacc[na][2]*inv1, v11 = oacc[na][3]*inv1;
        float2 p0; p0.x = v00; p0.y = v01;
        float2 p1; p1.x = v10; p1.y = v11;
        *(float2*)&g_y[i0] = p0;
        *(float2*)&g_y[i1] = p1;
        uint32_t hp, lp;
        split_pair(v00, v01, hp, lp);
        *(uint32_t*)&g_ah[i0] = hp; *(uint32_t*)&g_al[i0] = lp;
        split_pair(v10, v11, hp, lp);
        *(uint32_t*)&g_ah[i1] = hp; *(uint32_t*)&g_al[i1] = lp;
    }
    (void)dummy;
}

// ---------------------------------------------------------------------------
extern "C" void kernel_launch(void* const* d_in, const int* in_sizes, int n_in,
                              void* d_out, int out_size) {
    const float* x  = (const float*)d_in[0];
    const float* aw = (const float*)d_in[1];
    const float* ab = (const float*)d_in[2];
    const float* aA = (const float*)d_in[3];
    const float* aB = (const float*)d_in[4];
    const float* pw = (const float*)d_in[5];
    const float* pb = (const float*)d_in[6];
    const float* pA = (const float*)d_in[7];
    const float* pB = (const float*)d_in[8];
    (void)in_sizes; (void)n_in; (void)out_size;

    float* out  = (float*)d_out;
    float* outQ = out + (size_t)MM*CC;
    float* outK = out + (size_t)2*MM*CC;

    const int SMEM_GEMM = 2 * STAGE_BYTES + 1024;   // 132096 B (proven size)
    const int SMEM_FLASH = 2 * FS_STAGE + 1024;     // 65 KB
    cudaFuncSetAttribute(mma_gemm<0>, cudaFuncAttributeMaxDynamicSharedMemorySize, SMEM_GEMM);
    cudaFuncSetAttribute(mma_gemm<1>, cudaFuncAttributeMaxDynamicSharedMemorySize, SMEM_GEMM);
    cudaFuncSetAttribute(flash_mma, cudaFuncAttributeMaxDynamicSharedMemorySize, SMEM_FLASH);

    // 1) bf16 hi/lo splits of x, c_attn_w, c_proj_w
    conv_split<0><<<(MM*CC/4 + 255)/256, 256>>>(x, MM*CC/4);
    conv_split<1><<<(NQKV*CC/4 + 255)/256, 256>>>(aw, NQKV*CC/4);
    conv_split<2><<<(CC*CC/4 + 255)/256, 256>>>(pw, CC*CC/4);
    // 2) LoRA intermediate for c_attn
    lora_kernel<0><<<MM/8, 256>>>(x, aA);
    // 3) QKV GEMM (HMMA): q/k/v bf16-split scatter + query/key outputs
    mma_gemm<0><<<dim3(NQKV/128, MM/128), 128, SMEM_GEMM>>>(ab, aB, outQ, outK);
    // 4) Tensor-core causal flash attention -> g_y (+ bf16 split g_ah/g_al)
    flash_mma<<<dim3(TT/64, BB*HH), 128, SMEM_FLASH>>>(nullptr);
    // 5) LoRA intermediate for c_proj
    lora_kernel<1><<<MM/8, 256>>>(nullptr, pA);
    // 6) proj GEMM (HMMA) + bias + LoRA -> out
    mma_gemm<1><<<dim3(CC/128, MM/128), 128, SMEM_GEMM>>>(pb, pB, out, nullptr);
}

// round 10
// speedup vs baseline: 5.8054x; 1.2336x over previous
#include <cuda_runtime.h>
#include <cuda_bf16.h>
#include <cstdint>
#include <cstddef>

// Problem constants (fixed by the dataset)
#define BB 4
#define TT 2048
#define CC 1024
#define HH 16
#define DD 64
#define RR 8
#define MM (BB*TT)        // 8192
#define NQKV (3*CC)       // 3072

// Scratch (device globals -- referenced ONLY from device code).
__device__ float g_y[(size_t)MM*CC];         // attention output [B,T,C]
__device__ float g_t[(size_t)MM*RR];         // LoRA intermediate x@A^T
__device__ __nv_bfloat16 g_ah[(size_t)MM*CC];     // x, then attention y (hi)
__device__ __nv_bfloat16 g_al[(size_t)MM*CC];     // (lo)
__device__ __nv_bfloat16 g_bh[(size_t)NQKV*CC];   // c_attn_w hi
__device__ __nv_bfloat16 g_bl[(size_t)NQKV*CC];   // c_attn_w lo
__device__ __nv_bfloat16 g_pwh[(size_t)CC*CC];    // c_proj_w hi
__device__ __nv_bfloat16 g_pwl[(size_t)CC*CC];    // c_proj_w lo
// q/k/v in [B,H,T,D] as bf16 hi/lo split
__device__ __nv_bfloat16 g_qh[(size_t)BB*HH*TT*DD];
__device__ __nv_bfloat16 g_ql[(size_t)BB*HH*TT*DD];
__device__ __nv_bfloat16 g_kh[(size_t)BB*HH*TT*DD];
__device__ __nv_bfloat16 g_kl[(size_t)BB*HH*TT*DD];
__device__ __nv_bfloat16 g_vh[(size_t)BB*HH*TT*DD];
__device__ __nv_bfloat16 g_vl[(size_t)BB*HH*TT*DD];

// ---------------------------------------------------------------------------
// Helpers (base-target ISA only: cp.async / ldmatrix / mma.sync)
// ---------------------------------------------------------------------------
__device__ __forceinline__ uint32_t smem_u32(const void* p) {
    uint32_t a;
    asm("{ .reg .u64 t; cvta.to.shared.u64 t, %1; cvt.u32.u64 %0, t; }"
        : "=r"(a) : "l"(p));
    return a;
}
#define SWZ128(off) ((off) ^ (((off) >> 3) & 0x70))

#define CP_ASYNC16(dst, src) \
    asm volatile("cp.async.cg.shared.global [%0], [%1], 16;" :: "r"(dst), "l"(src))
#define CP_COMMIT() asm volatile("cp.async.commit_group;" ::: "memory")
#define CP_WAIT(n)  asm volatile("cp.async.wait_group %0;" :: "n"(n) : "memory")

#define LDSM_X4(r, a) \
    asm volatile("ldmatrix.sync.aligned.m8n8.x4.shared.b16 {%0,%1,%2,%3}, [%4];" \
                 : "=r"((r)[0]), "=r"((r)[1]), "=r"((r)[2]), "=r"((r)[3]) : "r"(a))
#define LDSM_X4_T(r, a) \
    asm volatile("ldmatrix.sync.aligned.m8n8.x4.trans.shared.b16 {%0,%1,%2,%3}, [%4];" \
                 : "=r"((r)[0]), "=r"((r)[1]), "=r"((r)[2]), "=r"((r)[3]) : "r"(a))

#define MMA16816(d, a, b0, b1) \
    asm volatile("mma.sync.aligned.m16n8k16.row.col.f32.bf16.bf16.f32 " \
                 "{%0,%1,%2,%3}, {%4,%5,%6,%7}, {%8,%9}, {%0,%1,%2,%3};" \
                 : "+f"((d)[0]), "+f"((d)[1]), "+f"((d)[2]), "+f"((d)[3]) \
                 : "r"((a)[0]), "r"((a)[1]), "r"((a)[2]), "r"((a)[3]), \
                   "r"(b0), "r"(b1))

// split a float pair into bf16 hi pair + bf16 lo (residual) pair
__device__ __forceinline__ void split_pair(float a, float b, uint32_t& hi, uint32_t& lo) {
    __nv_bfloat162 h = __floats2bfloat162_rn(a, b);
    float ra = a - __bfloat162float(h.x);
    float rb = b - __bfloat162float(h.y);
    __nv_bfloat162 l = __floats2bfloat162_rn(ra, rb);
    hi = *(uint32_t*)&h;
    lo = *(uint32_t*)&l;
}

// ---------------------------------------------------------------------------
// fp32 -> bf16 hi/lo split conversion. DST selects device-global target
// INSIDE device code: 0 -> g_ah/g_al, 1 -> g_bh/g_bl, 2 -> g_pwh/g_pwl.
// ---------------------------------------------------------------------------
template<int DST>
__global__ void conv_split(const float* __restrict__ src, int n4) {
    int i = blockIdx.x * blockDim.x + threadIdx.x;
    if (i >= n4) return;
    float4 v = ((const float4*)src)[i];
    __nv_bfloat16* H = (DST == 0) ? g_ah : ((DST == 1) ? g_bh : g_pwh);
    __nv_bfloat16* L = (DST == 0) ? g_al : ((DST == 1) ? g_bl : g_pwl);
    uint32_t h0, l0, h1, l1;
    split_pair(v.x, v.y, h0, l0);
    split_pair(v.z, v.w, h1, l1);
    ((uint32_t*)H)[2*i]   = h0;
    ((uint32_t*)H)[2*i+1] = h1;
    ((uint32_t*)L)[2*i]   = l0;
    ((uint32_t*)L)[2*i+1] = l1;
}

// ---------------------------------------------------------------------------
// LoRA intermediate: t[m, r] = sum_k X[m,k] * A[r,k]   (one warp per row m)
// ---------------------------------------------------------------------------
template<int SRC>
__global__ void lora_kernel(const float* __restrict__ Xin, const float* __restrict__ A) {
    const float* X = (SRC == 1) ? g_y : Xin;
    int warp = (blockIdx.x * blockDim.x + threadIdx.x) >> 5;
    int lane = threadIdx.x & 31;
    const float* xr = X + (size_t)warp * CC;
    float acc[RR];
#pragma unroll
    for (int r = 0; r < RR; r++) acc[r] = 0.f;
    for (int k = lane; k < CC; k += 32) {
        float xv = xr[k];
#pragma unroll
        for (int r = 0; r < RR; r++) acc[r] = fmaf(xv, __ldg(&A[r*CC + k]), acc[r]);
    }
#pragma unroll
    for (int r = 0; r < RR; r++) {
        acc[r] += __shfl_xor_sync(0xffffffffu, acc[r], 16);
        acc[r] += __shfl_xor_sync(0xffffffffu, acc[r], 8);
        acc[r] += __shfl_xor_sync(0xffffffffu, acc[r], 4);
        acc[r] += __shfl_xor_sync(0xffffffffu, acc[r], 2);
        acc[r] += __shfl_xor_sync(0xffffffffu, acc[r], 1);
    }
    if (lane == 0) {
#pragma unroll
        for (int r = 0; r < RR; r++) g_t[(size_t)warp*RR + r] = acc[r];
    }
}

// ---------------------------------------------------------------------------
// bf16-split HMMA GEMM (mma.sync m16n8k16) + bias + rank-8 LoRA epilogue.
// CTA tile 128(M) x 256(N), 256 threads: 8 warps of 64x64 (wm=wid>>2, wn=wid&3)
// -> 2 warps per SMSP AND 85 B smem-read per MMA. Inner loop is TERM-MAJOR
// (hh, hl, lh) so consecutive MMAs hit 8 different accumulators.
// K chunks of 64, double-buffered cp.async, stage = 96KB, smem 193KB.
// MODE 0: QKV (weights g_bh/g_bl) -> q/k/v hi/lo scatter + query/key outs.
// MODE 1: proj (weights g_pwh/g_pwl) -> plain [M,C] fp32 output.
// ---------------------------------------------------------------------------
#define STAGE_BYTES 98304
#define OFF_AH 0
#define OFF_AL 16384
#define OFF_BH 32768
#define OFF_BL 65536

template<int MODE>
__global__ void __launch_bounds__(256) mma_gemm(const float* __restrict__ bias,
                                                const float* __restrict__ Blora,
                                                float* __restrict__ out0,
                                                float* __restrict__ out1)
{
    extern __shared__ char smem_raw[];
    uint32_t raw = smem_u32(smem_raw);
    uint32_t sb = (raw + 1023u) & ~1023u;

    const __nv_bfloat16* Wh = (MODE == 0) ? g_bh : g_pwh;   // device-side select
    const __nv_bfloat16* Wl = (MODE == 0) ? g_bl : g_pwl;

    int tid  = threadIdx.x;
    int wid  = tid >> 5, lane = tid & 31;
    int wm   = wid >> 2;       // 0..1 -> 64-row slab
    int wn   = wid & 3;        // 0..3 -> 64-col slab
    int bm = blockIdx.y * 128;
    int bn = blockIdx.x * 256;

    int lrow = tid >> 3;       // 0..31
    int lq   = tid & 7;        // uint4 index within 128B row

    float acc[4][8][4];
#pragma unroll
    for (int i = 0; i < 4; i++)
#pragma unroll
        for (int j = 0; j < 8; j++)
#pragma unroll
            for (int c = 0; c < 4; c++) acc[i][j][c] = 0.f;

    auto load_chunk = [&](int stage, int k0) {
        uint32_t base = sb + stage * STAGE_BYTES;
        // A hi/lo: 128 rows x 64 bf16 (128B/row)
#pragma unroll
        for (int i = 0; i < 4; i++) {
            int row = lrow + i * 32;
            uint32_t boff = SWZ128((uint32_t)(row * 128 + lq * 16));
            size_t go = (size_t)(bm + row) * CC + k0 + lq * 8;
            CP_ASYNC16(base + OFF_AH + boff, g_ah + go);
            CP_ASYNC16(base + OFF_AL + boff, g_al + go);
        }
        // B hi/lo: 256 rows x 64 bf16
#pragma unroll
        for (int i = 0; i < 8; i++) {
            int row = lrow + i * 32;
            uint32_t boff = SWZ128((uint32_t)(row * 128 + lq * 16));
            size_t go = (size_t)(bn + row) * CC + k0 + lq * 8;
            CP_ASYNC16(base + OFF_BH + boff, Wh + go);
            CP_ASYNC16(base + OFF_BL + boff, Wl + go);
        }
        CP_COMMIT();
    };

    const int NCHUNK = CC / 64;
    load_chunk(0, 0);

    for (int ch = 0; ch < NCHUNK; ++ch) {
        if (ch + 1 < NCHUNK) {
            load_chunk((ch + 1) & 1, (ch + 1) * 64);
            CP_WAIT(1);
        } else {
            CP_WAIT(0);
        }
        __syncthreads();
        uint32_t base = sb + (ch & 1) * STAGE_BYTES;

#pragma unroll
        for (int ks = 0; ks < 4; ks++) {
            uint32_t ah[4][4], al[4][4];
#pragma unroll
            for (int ma = 0; ma < 4; ma++) {
                int row = wm * 64 + ma * 16 + (lane & 15);
                uint32_t kb = ks * 32 + ((lane >> 4) << 4);
                uint32_t off = SWZ128((uint32_t)(row * 128) + kb);
                LDSM_X4(ah[ma], base + OFF_AH + off);
                LDSM_X4(al[ma], base + OFF_AL + off);
            }
#pragma unroll
            for (int nb = 0; nb < 4; nb++) {
                uint32_t bh4[4], bl4[4];
                int row = wn * 64 + nb * 16 + (lane & 7) + ((lane >> 4) << 3);
                uint32_t kb = ks * 32 + (((lane >> 3) & 1) << 4);
                uint32_t off = SWZ128((uint32_t)(row * 128) + kb);
                LDSM_X4(bh4, base + OFF_BH + off);
                LDSM_X4(bl4, base + OFF_BL + off);
                // term-major: 8 independent MMAs between accumulator reuses
#pragma unroll
                for (int ma = 0; ma < 4; ma++)
#pragma unroll
                    for (int h = 0; h < 2; h++)
                        MMA16816(acc[ma][nb*2+h], ah[ma], bh4[2*h], bh4[2*h+1]);
#pragma unroll
                for (int ma = 0; ma < 4; ma++)
#pragma unroll
                    for (int h = 0; h < 2; h++)
                        MMA16816(acc[ma][nb*2+h], ah[ma], bl4[2*h], bl4[2*h+1]);
#pragma unroll
                for (int ma = 0; ma < 4; ma++)
#pragma unroll
                    for (int h = 0; h < 2; h++)
                        MMA16816(acc[ma][nb*2+h], al[ma], bh4[2*h], bh4[2*h+1]);
            }
        }
        __syncthreads();
    }

    // ---- epilogue: + bias + LoRA, write out ----
#pragma unroll
    for (int ma = 0; ma < 4; ma++) {
        int m0 = bm + wm * 64 + ma * 16 + (lane >> 2);
        int m1 = m0 + 8;
        float4 t0a = *(const float4*)&g_t[(size_t)m0 * RR];
        float4 t0b = *(const float4*)&g_t[(size_t)m0 * RR + 4];
        float4 t1a = *(const float4*)&g_t[(size_t)m1 * RR];
        float4 t1b = *(const float4*)&g_t[(size_t)m1 * RR + 4];
#pragma unroll
        for (int na = 0; na < 8; na++) {
            int n0 = bn + wn * 64 + na * 8 + (lane & 3) * 2;
            int n1 = n0 + 1;
            float4 b0a = *(const float4*)&Blora[(size_t)n0 * RR];
            float4 b0b = *(const float4*)&Blora[(size_t)n0 * RR + 4];
            float4 b1a = *(const float4*)&Blora[(size_t)n1 * RR];
            float4 b1b = *(const float4*)&Blora[(size_t)n1 * RR + 4];
            float bs0 = __ldg(&bias[n0]), bs1 = __ldg(&bias[n1]);
            float v00 = acc[ma][na][0] + bs0
                + t0a.x*b0a.x + t0a.y*b0a.y + t0a.z*b0a.z + t0a.w*b0a.w
                + t0b.x*b0b.x + t0b.y*b0b.y + t0b.z*b0b.z + t0b.w*b0b.w;
            float v01 = acc[ma][na][1] + bs1
                + t0a.x*b1a.x + t0a.y*b1a.y + t0a.z*b1a.z + t0a.w*b1a.w
                + t0b.x*b1b.x + t0b.y*b1b.y + t0b.z*b1b.z + t0b.w*b1b.w;
            float v10 = acc[ma][na][2] + bs0
                + t1a.x*b0a.x + t1a.y*b0a.y + t1a.z*b0a.z + t1a.w*b0a.w
                + t1b.x*b0b.x + t1b.y*b0b.y + t1b.z*b0b.z + t1b.w*b0b.w;
            float v11 = acc[ma][na][3] + bs1
                + t1a.x*b1a.x + t1a.y*b1a.y + t1a.z*b1a.z + t1a.w*b1a.w
                + t1b.x*b1b.x + t1b.y*b1b.y + t1b.z*b1b.z + t1b.w*b1b.w;

            if (MODE == 0) {
                int sec = n0 >> 10;            // 0=q, 1=k, 2=v
                int cci = n0 & 1023;
                int h = cci >> 6, dd = cci & 63;
                __nv_bfloat16* dh = (sec == 0) ? g_qh : ((sec == 1) ? g_kh : g_vh);
                __nv_bfloat16* dl = (sec == 0) ? g_ql : ((sec == 1) ? g_kl : g_vl);
                {
                    int bi = m0 >> 11, ti = m0 & 2047;
                    size_t idx = ((size_t)((bi*HH) + h)*TT + ti)*DD + dd;
                    uint32_t hp, lp; split_pair(v00, v01, hp, lp);
                    *(uint32_t*)&dh[idx] = hp;
                    *(uint32_t*)&dl[idx] = lp;
                    float2 p; p.x = v00; p.y = v01;
                    if (sec == 0)      *(float2*)&out0[(size_t)m0*CC + cci] = p;
                    else if (sec == 1) *(float2*)&out1[(size_t)m0*CC + cci] = p;
                }
                {
                    int bi = m1 >> 11, ti = m1 & 2047;
                    size_t idx = ((size_t)((bi*HH) + h)*TT + ti)*DD + dd;
                    uint32_t hp, lp; split_pair(v10, v11, hp, lp);
                    *(uint32_t*)&dh[idx] = hp;
                    *(uint32_t*)&dl[idx] = lp;
                    float2 p; p.x = v10; p.y = v11;
                    if (sec == 0)      *(float2*)&out0[(size_t)m1*CC + cci] = p;
                    else if (sec == 1) *(float2*)&out1[(size_t)m1*CC + cci] = p;
                }
            } else {
                float2 p0; p0.x = v00; p0.y = v01;
                float2 p1; p1.x = v10; p1.y = v11;
                *(float2*)&out0[(size_t)m0*CC + n0] = p0;
                *(float2*)&out0[(size_t)m1*CC + n0] = p1;
            }
        }
    }
}

// ---------------------------------------------------------------------------
// Tensor-core causal flash attention (bf16 split, fp32 softmax).
// CTA: 64 Q-rows, 128 threads (4 warps x 16 rows). K/V tiles 64 x 64,
// hi/lo split, cp.async double-buffered. S frags reused as P frags.
// ---------------------------------------------------------------------------
#define FS_STAGE 32768
#define FS_KH 0
#define FS_KL 8192
#define FS_VH 16384
#define FS_VL 24576

__global__ void __launch_bounds__(128) flash_mma(float* __restrict__ dummy) {
    extern __shared__ char smem_raw[];
    uint32_t raw = smem_u32(smem_raw);
    uint32_t sb = (raw + 1023u) & ~1023u;

    int bh = blockIdx.y;
    int qi = gridDim.x - 1 - (int)blockIdx.x;   // long blocks first
    int tid = threadIdx.x;
    int wid = tid >> 5, lane = tid & 31;
    int row0 = qi * 64;

    const __nv_bfloat16* Qh = g_qh + ((size_t)bh*TT + row0) * DD;
    const __nv_bfloat16* Ql = g_ql + ((size_t)bh*TT + row0) * DD;
    const __nv_bfloat16* Kh = g_kh + (size_t)bh*TT*DD;
    const __nv_bfloat16* Kl = g_kl + (size_t)bh*TT*DD;
    const __nv_bfloat16* Vh = g_vh + (size_t)bh*TT*DD;
    const __nv_bfloat16* Vl = g_vl + (size_t)bh*TT*DD;

    auto load_tile = [&](uint32_t dst, const __nv_bfloat16* src) {
#pragma unroll
        for (int i = 0; i < 4; i++) {
            int e = tid + i * 128;
            int row = e >> 3, q = e & 7;
            CP_ASYNC16(dst + SWZ128((uint32_t)(row * 128 + q * 16)), src + row * 64 + q * 8);
        }
    };

    // ---- load Q into stage0 K area, move to registers ----
    load_tile(sb + FS_KH, Qh);
    load_tile(sb + FS_KL, Ql);
    CP_COMMIT();
    CP_WAIT(0);
    __syncthreads();
    uint32_t qh[4][4], ql[4][4];
#pragma unroll
    for (int k = 0; k < 4; k++) {
        int row = wid * 16 + (lane & 15);
        uint32_t kb = k * 32 + ((lane >> 4) << 4);
        uint32_t off = SWZ128((uint32_t)(row * 128) + kb);
        LDSM_X4(qh[k], sb + FS_KH + off);
        LDSM_X4(ql[k], sb + FS_KL + off);
    }
    __syncthreads();

    float oacc[8][4];
#pragma unroll
    for (int i = 0; i < 8; i++)
#pragma unroll
        for (int c = 0; c < 4; c++) oacc[i][c] = 0.f;
    float m_pr[2] = { -1e30f, -1e30f };
    float l_pr[2] = { 0.f, 0.f };

    int jmax = qi;
    auto load_kv = [&](int stage, int j) {
        uint32_t base = sb + stage * FS_STAGE;
        size_t o = (size_t)j * 64 * DD;
        load_tile(base + FS_KH, Kh + o);
        load_tile(base + FS_KL, Kl + o);
        load_tile(base + FS_VH, Vh + o);
        load_tile(base + FS_VL, Vl + o);
        CP_COMMIT();
    };
    load_kv(0, 0);

    for (int j = 0; j <= jmax; ++j) {
        if (j < jmax) { load_kv((j + 1) & 1, j + 1); CP_WAIT(1); }
        else          { CP_WAIT(0); }
        __syncthreads();
        uint32_t base = sb + (j & 1) * FS_STAGE;

        // ---- S = Q K^T (3-term split) ----
        float sacc[8][4];
#pragma unroll
        for (int i = 0; i < 8; i++)
#pragma unroll
            for (int c = 0; c < 4; c++) sacc[i][c] = 0.f;
#pragma unroll
        for (int k = 0; k < 4; k++) {
#pragma unroll
            for (int np = 0; np < 4; np++) {
                uint32_t kh4[4], kl4[4];
                int row = np * 16 + (lane & 7) + ((lane >> 3) & 1) * 8;
                uint32_t col = k * 32 + ((lane >> 4) << 4);
                uint32_t off = SWZ128((uint32_t)(row * 128) + col);
                LDSM_X4(kh4, base + FS_KH + off);
                LDSM_X4(kl4, base + FS_KL + off);
                MMA16816(sacc[2*np],   qh[k], kh4[0], kh4[2]);
                MMA16816(sacc[2*np+1], qh[k], kh4[1], kh4[3]);
                MMA16816(sacc[2*np],   qh[k], kl4[0], kl4[2]);
                MMA16816(sacc[2*np+1], qh[k], kl4[1], kl4[3]);
                MMA16816(sacc[2*np],   ql[k], kh4[0], kh4[2]);
                MMA16816(sacc[2*np+1], ql[k], kh4[1], kh4[3]);
            }
        }

        // ---- scale + causal mask + online softmax ----
        bool diag = (j == jmax);
        int rl0 = wid * 16 + (lane >> 2);
        float mx[2] = { -1e30f, -1e30f };
#pragma unroll
        for (int na = 0; na < 8; na++) {
#pragma unroll
            for (int c = 0; c < 4; c++) {
                float s = sacc[na][c] * 0.125f;
                if (diag) {
                    int colg = na * 8 + (lane & 3) * 2 + (c & 1);
                    int rowg = rl0 + ((c >> 1) << 3);
                    if (colg > rowg) s = -1e30f;
                }
                sacc[na][c] = s;
                int hsel = c >> 1;
                mx[hsel] = fmaxf(mx[hsel], s);
            }
        }
#pragma unroll
        for (int h = 0; h < 2; h++) {
            mx[h] = fmaxf(mx[h], __shfl_xor_sync(0xffffffffu, mx[h], 1));
            mx[h] = fmaxf(mx[h], __shfl_xor_sync(0xffffffffu, mx[h], 2));
        }
        float m_new[2], alpha[2], lsum[2] = { 0.f, 0.f };
#pragma unroll
        for (int h = 0; h < 2; h++) {
            m_new[h] = fmaxf(m_pr[h], mx[h]);
            alpha[h] = __expf(m_pr[h] - m_new[h]);
            m_pr[h] = m_new[h];
        }
#pragma unroll
        for (int na = 0; na < 8; na++) {
#pragma unroll
            for (int c = 0; c < 4; c++) {
                int hsel = c >> 1;
                float p = __expf(sacc[na][c] - m_new[hsel]);
                sacc[na][c] = p;
                lsum[hsel] += p;
            }
        }
#pragma unroll
        for (int h = 0; h < 2; h++) {
            lsum[h] += __shfl_xor_sync(0xffffffffu, lsum[h], 1);
            lsum[h] += __shfl_xor_sync(0xffffffffu, lsum[h], 2);
            l_pr[h] = l_pr[h] * alpha[h] + lsum[h];
        }
#pragma unroll
        for (int na = 0; na < 8; na++) {
            oacc[na][0] *= alpha[0]; oacc[na][1] *= alpha[0];
            oacc[na][2] *= alpha[1]; oacc[na][3] *= alpha[1];
        }

        // ---- O += P V (3-term split) ----
#pragma unroll
        for (int s = 0; s < 4; s++) {
            uint32_t ph[4], pl[4];
            split_pair(sacc[2*s][0],   sacc[2*s][1],   ph[0], pl[0]);
            split_pair(sacc[2*s][2],   sacc[2*s][3],   ph[1], pl[1]);
            split_pair(sacc[2*s+1][0], sacc[2*s+1][1], ph[2], pl[2]);
            split_pair(sacc[2*s+1][2], sacc[2*s+1][3], ph[3], pl[3]);
#pragma unroll
            for (int np = 0; np < 4; np++) {
                uint32_t vh4[4], vl4[4];
                int row = s * 16 + (lane & 7) + ((lane >> 3) & 1) * 8;
                uint32_t col = np * 32 + ((lane >> 4) << 4);
                uint32_t off = SWZ128((uint32_t)(row * 128) + col);
                LDSM_X4_T(vh4, base + FS_VH + off);
                LDSM_X4_T(vl4, base + FS_VL + off);
                MMA16816(oacc[2*np],   ph, vh4[0], vh4[1]);
                MMA16816(oacc[2*np+1], ph, vh4[2], vh4[3]);
                MMA16816(oacc[2*np],   ph, vl4[0], vl4[1]);
                MMA16816(oacc[2*np+1], ph, vl4[2], vl4[3]);
                MMA16816(oacc[2*np],   pl, vh4[0], vh4[1]);
                MMA16816(oacc[2*np+1], pl, vh4[2], vh4[3]);
            }
        }
        __syncthreads();
    }

    // ---- epilogue: normalize, write fp32 g_y + bf16 split g_ah/g_al ----
    float inv0 = 1.0f / l_pr[0];
    float inv1 = 1.0f / l_pr[1];
    int h = bh & (HH - 1), bi = bh >> 4;
    int t0 = row0 + wid * 16 + (lane >> 2);
    int t1 = t0 + 8;
    int dbase = h * DD + (lane & 3) * 2;
#pragma unroll
    for (int na = 0; na < 8; na++) {
        int d = dbase + na * 8;
        size_t i0 = ((size_t)(bi*TT + t0))*CC + d;
        size_t i1 = ((size_t)(bi*TT + t1))*CC + d;
        float v00 = oacc[na][0]*inv0, v01 = oacc[na][1]*inv0;
        float v10 = oacc[na][2]*inv1, v11 = oacc[na][3]*inv1;
        float2 p0; p0.x = v00; p0.y = v01;
        float2 p1; p1.x = v10; p1.y = v11;
        *(float2*)&g_y[i0] = p0;
        *(float2*)&g_y[i1] = p1;
        uint32_t hp, lp;
        split_pair(v00, v01, hp, lp);
        *(uint32_t*)&g_ah[i0] = hp; *(uint32_t*)&g_al[i0] = lp;
        split_pair(v10, v11, hp, lp);
        *(uint32_t*)&g_ah[i1] = hp; *(uint32_t*)&g_al[i1] = lp;
    }
    (void)dummy;
}

// ---------------------------------------------------------------------------
extern "C" void kernel_launch(void* const* d_in, const int* in_sizes, int n_in,
                              void* d_out, int out_size) {
    const float* x  = (const float*)d_in[0];
    const float* aw = (const float*)d_in[1];
    const float* ab = (const float*)d_in[2];
    const float* aA = (const float*)d_in[3];
    const float* aB = (const float*)d_in[4];
    const float* pw = (const float*)d_in[5];
    const float* pb = (const float*)d_in[6];
    const float* pA = (const float*)d_in[7];
    const float* pB = (const float*)d_in[8];
    (void)in_sizes; (void)n_in; (void)out_size;

    float* out  = (float*)d_out;
    float* outQ = out + (size_t)MM*CC;
    float* outK = out + (size_t)2*MM*CC;

    const int SMEM_GEMM = 2 * STAGE_BYTES + 1024;   // 197632 B (<= 227KB opt-in)
    const int SMEM_FLASH = 2 * FS_STAGE + 1024;     // 65 KB
    cudaFuncSetAttribute(mma_gemm<0>, cudaFuncAttributeMaxDynamicSharedMemorySize, SMEM_GEMM);
    cudaFuncSetAttribute(mma_gemm<1>, cudaFuncAttributeMaxDynamicSharedMemorySize, SMEM_GEMM);
    cudaFuncSetAttribute(flash_mma, cudaFuncAttributeMaxDynamicSharedMemorySize, SMEM_FLASH);

    // 1) bf16 hi/lo splits of x, c_attn_w, c_proj_w
    conv_split<0><<<(MM*CC/4 + 255)/256, 256>>>(x, MM*CC/4);
    conv_split<1><<<(NQKV*CC/4 + 255)/256, 256>>>(aw, NQKV*CC/4);
    conv_split<2><<<(CC*CC/4 + 255)/256, 256>>>(pw, CC*CC/4);
    // 2) LoRA intermediate for c_attn
    lora_kernel<0><<<MM/8, 256>>>(x, aA);
    // 3) QKV GEMM (HMMA): q/k/v bf16-split scatter + query/key outputs
    mma_gemm<0><<<dim3(NQKV/256, MM/128), 256, SMEM_GEMM>>>(ab, aB, outQ, outK);
    // 4) Tensor-core causal flash attention -> g_y (+ bf16 split g_ah/g_al)
    flash_mma<<<dim3(TT/64, BB*HH), 128, SMEM_FLASH>>>(nullptr);
    // 5) LoRA intermediate for c_proj
    lora_kernel<1><<<MM/8, 256>>>(nullptr, pA);
    // 6) proj GEMM (HMMA) + bias + LoRA -> out
    mma_gemm<1><<<dim3(CC/256, MM/128), 256, SMEM_GEMM>>>(pb, pB, out, nullptr);
}